// round 2
// baseline (speedup 1.0000x reference)
#include <cuda_runtime.h>
#include <cuda_bf16.h>
#include <cstdint>

// Problem sizes (fixed by reference setup_inputs)
#define BB 8
#define TT 2048
#define CC 1024
#define MM (BB*TT)          // 16384 rows

// ---------------- scratch (static device arrays; no allocation) -------------
__device__ float g_xn    [(size_t)MM * CC];        // LN1 output        64 MB
__device__ float g_kvr   [(size_t)MM * 3 * CC];    // k,v,r (mixed)    192 MB
__device__ float g_x1    [(size_t)MM * CC];        // x after time-mix  64 MB
__device__ float g_xn2   [(size_t)MM * CC];        // LN2 output        64 MB
__device__ float g_rr    [(size_t)MM * CC];        // channel-mix gate  64 MB
__device__ float g_hidden[(size_t)MM * 4 * CC];    // relu^2 hidden    256 MB

__device__ __forceinline__ float sigmoidf_(float z) {
    return 1.0f / (1.0f + __expf(-z));
}

// ---------------- LayerNorm 1: xn = LN(x; g1,b1) ----------------------------
__global__ void ln1_kernel(const float* __restrict__ x,
                           const float* __restrict__ g,
                           const float* __restrict__ b,
                           float* __restrict__ out) {
    int row = blockIdx.x;
    const float4* xr = (const float4*)(x + (size_t)row * CC);
    float4 v = xr[threadIdx.x];
    float s  = v.x + v.y + v.z + v.w;
    float q  = v.x*v.x + v.y*v.y + v.z*v.z + v.w*v.w;
    int lane = threadIdx.x & 31, wid = threadIdx.x >> 5;
    #pragma unroll
    for (int o = 16; o; o >>= 1) {
        s += __shfl_xor_sync(0xffffffffu, s, o);
        q += __shfl_xor_sync(0xffffffffu, q, o);
    }
    __shared__ float s_s[8], s_q[8];
    if (!lane) { s_s[wid] = s; s_q[wid] = q; }
    __syncthreads();
    if (threadIdx.x == 0) {
        float a = 0.f, c2 = 0.f;
        #pragma unroll
        for (int i = 0; i < 8; i++) { a += s_s[i]; c2 += s_q[i]; }
        s_s[0] = a; s_q[0] = c2;
    }
    __syncthreads();
    float mean = s_s[0] * (1.0f / CC);
    float var  = s_q[0] * (1.0f / CC) - mean * mean;
    float rstd = rsqrtf(var + 1e-5f);
    float4 gv = ((const float4*)g)[threadIdx.x];
    float4 bv = ((const float4*)b)[threadIdx.x];
    float4 o4;
    o4.x = (v.x - mean) * rstd * gv.x + bv.x;
    o4.y = (v.y - mean) * rstd * gv.y + bv.y;
    o4.z = (v.z - mean) * rstd * gv.z + bv.z;
    o4.w = (v.w - mean) * rstd * gv.w + bv.w;
    ((float4*)(out + (size_t)row * CC))[threadIdx.x] = o4;
}

// ---------------- LayerNorm 2 + rr gate -------------------------------------
// xn2 = LN(x1; g2,b2);  rr = sigmoid(xn2*cmr + xp*(1-cmr)),
// xp[b,t] = x1[b,t-1], xp[b,0] = x1[b,T-1]  (wrap, per reference)
__global__ void ln2_rr_kernel(const float* __restrict__ x1,
                              const float* __restrict__ g,
                              const float* __restrict__ b,
                              const float* __restrict__ cmr,
                              float* __restrict__ xn2,
                              float* __restrict__ rr) {
    int row = blockIdx.x;
    const float4* xr = (const float4*)(x1 + (size_t)row * CC);
    float4 v = xr[threadIdx.x];
    float s  = v.x + v.y + v.z + v.w;
    float q  = v.x*v.x + v.y*v.y + v.z*v.z + v.w*v.w;
    int lane = threadIdx.x & 31, wid = threadIdx.x >> 5;
    #pragma unroll
    for (int o = 16; o; o >>= 1) {
        s += __shfl_xor_sync(0xffffffffu, s, o);
        q += __shfl_xor_sync(0xffffffffu, q, o);
    }
    __shared__ float s_s[8], s_q[8];
    if (!lane) { s_s[wid] = s; s_q[wid] = q; }
    __syncthreads();
    if (threadIdx.x == 0) {
        float a = 0.f, c2 = 0.f;
        #pragma unroll
        for (int i = 0; i < 8; i++) { a += s_s[i]; c2 += s_q[i]; }
        s_s[0] = a; s_q[0] = c2;
    }
    __syncthreads();
    float mean = s_s[0] * (1.0f / CC);
    float var  = s_q[0] * (1.0f / CC) - mean * mean;
    float rstd = rsqrtf(var + 1e-5f);
    float4 gv = ((const float4*)g)[threadIdx.x];
    float4 bv = ((const float4*)b)[threadIdx.x];
    float4 o4;
    o4.x = (v.x - mean) * rstd * gv.x + bv.x;
    o4.y = (v.y - mean) * rstd * gv.y + bv.y;
    o4.z = (v.z - mean) * rstd * gv.z + bv.z;
    o4.w = (v.w - mean) * rstd * gv.w + bv.w;
    ((float4*)(xn2 + (size_t)row * CC))[threadIdx.x] = o4;

    int t = row & (TT - 1);
    int prow = (t == 0) ? (row + TT - 1) : (row - 1);
    float4 xp = ((const float4*)(x1 + (size_t)prow * CC))[threadIdx.x];
    float4 cr = ((const float4*)cmr)[threadIdx.x];
    float4 r4;
    r4.x = sigmoidf_(xp.x + cr.x * (o4.x - xp.x));
    r4.y = sigmoidf_(xp.y + cr.y * (o4.y - xp.y));
    r4.z = sigmoidf_(xp.z + cr.z * (o4.z - xp.z));
    r4.w = sigmoidf_(xp.w + cr.w * (o4.w - xp.w));
    ((float4*)(rr + (size_t)row * CC))[threadIdx.x] = r4;
}

// ---------------- WKV scan (fused x1 = x + r*y) ------------------------------
// One thread per (b,c). Depth-8 register prefetch ring hides DRAM latency.
#define PF 8
__global__ void wkv_kernel(const float* __restrict__ kvr,
                           const float* __restrict__ x,
                           const float* __restrict__ wd,
                           const float* __restrict__ uf,
                           float* __restrict__ x1,
                           float* __restrict__ out_state) {
    int gid = blockIdx.x * blockDim.x + threadIdx.x;   // 0..8191
    int b = gid >> 10, c = gid & (CC - 1);
    float w = wd[c], u = uf[c];
    float aa = 0.0f, bb = -1e38f;
    size_t kbase = (size_t)b * TT * (3 * CC) + c;
    size_t xbase = (size_t)b * TT * CC + c;

    float pk[PF], pv[PF], pr[PF], px[PF];
    #pragma unroll
    for (int i = 0; i < PF; i++) {
        size_t ko = kbase + (size_t)i * (3 * CC);
        pk[i] = kvr[ko];
        pv[i] = kvr[ko + CC];
        pr[i] = kvr[ko + 2 * CC];
        px[i] = x[xbase + (size_t)i * CC];
    }

    for (int t0 = 0; t0 < TT; t0 += PF) {
        #pragma unroll
        for (int i = 0; i < PF; i++) {
            int t = t0 + i;
            float kk = pk[i], vv = pv[i], r = pr[i], xv = px[i];
            int tn = t + PF;
            if (tn < TT) {
                size_t ko = kbase + (size_t)tn * (3 * CC);
                pk[i] = kvr[ko];
                pv[i] = kvr[ko + CC];
                pr[i] = kvr[ko + 2 * CC];
                px[i] = x[xbase + (size_t)tn * CC];
            }
            // output
            float ww = u + kk;
            float p  = fmaxf(bb, ww);
            float e1 = __expf(bb - p);
            float e2 = __expf(ww - p);
            float y  = __fdividef(e1 * aa + e2 * vv, e1 + e2 + 1e-8f);
            x1[xbase + (size_t)t * CC] = xv + r * y;
            // state update
            float w2 = w + bb;
            float p2 = fmaxf(w2, kk);
            float ea = __expf(w2 - p2);
            float eb = __expf(kk - p2);
            aa = ea * aa + eb * vv;
            bb = p2 + __logf(ea + eb + 1e-8f);
        }
    }
    out_state[(size_t)gid * 2 + 0] = aa;
    out_state[(size_t)gid * 2 + 1] = bb;
}

// ---------------- SGEMM 128x128x8, 8x8/thread, fused epilogues ---------------
// EPI=1: time-mix epilogue -> g_kvr (e0=x, e1=tmk, e2=tmv, e3=tmr)
// EPI=2: channel-mix relu^2 epilogue -> g_hidden (e0=x1, e1=cmk)
// EPI=3: final out = x1 + rr*acc (e0=x1, e1=rr)
template <int EPI>
__global__ void __launch_bounds__(256)
sgemm_kernel(const float* __restrict__ A, const float* __restrict__ Bw,
             float* __restrict__ Cout, int K, int N,
             const float* __restrict__ e0, const float* __restrict__ e1,
             const float* __restrict__ e2, const float* __restrict__ e3) {
    __shared__ float As[8][128];
    __shared__ float Bs[8][128];
    const int tid = threadIdx.x;
    const int m0 = blockIdx.y * 128;
    const int n0 = blockIdx.x * 128;
    const int tx = tid & 15, ty = tid >> 4;

    const int arow = tid >> 1;          // 0..127
    const int acol = (tid & 1) * 4;     // 0 or 4
    const int brow = tid >> 5;          // 0..7
    const int bcol = (tid & 31) * 4;    // 0..124

    const float* Ap = A + (size_t)(m0 + arow) * K + acol;
    const float* Bp = Bw + (size_t)brow * N + n0 + bcol;

    float acc[8][8];
    #pragma unroll
    for (int i = 0; i < 8; i++)
        #pragma unroll
        for (int j = 0; j < 8; j++) acc[i][j] = 0.f;

    for (int k0 = 0; k0 < K; k0 += 8) {
        float4 av = *(const float4*)Ap;  Ap += 8;
        float4 bv = *(const float4*)Bp;  Bp += (size_t)8 * N;
        As[acol + 0][arow] = av.x;
        As[acol + 1][arow] = av.y;
        As[acol + 2][arow] = av.z;
        As[acol + 3][arow] = av.w;
        *(float4*)&Bs[brow][bcol] = bv;
        __syncthreads();
        #pragma unroll
        for (int kk = 0; kk < 8; kk++) {
            float a[8], bq[8];
            *(float4*)(a)     = *(const float4*)&As[kk][ty * 8];
            *(float4*)(a + 4) = *(const float4*)&As[kk][ty * 8 + 4];
            *(float4*)(bq)     = *(const float4*)&Bs[kk][tx * 8];
            *(float4*)(bq + 4) = *(const float4*)&Bs[kk][tx * 8 + 4];
            #pragma unroll
            for (int i = 0; i < 8; i++)
                #pragma unroll
                for (int j = 0; j < 8; j++)
                    acc[i][j] = fmaf(a[i], bq[j], acc[i][j]);
        }
        __syncthreads();
    }

    #pragma unroll
    for (int i = 0; i < 8; i++) {
        int m = m0 + ty * 8 + i;
        int t = m & (TT - 1);
        #pragma unroll
        for (int j = 0; j < 8; j++) {
            int n = n0 + tx * 8 + j;
            float v = acc[i][j];
            if (EPI == 1) {
                int c   = n & (CC - 1);
                int seg = n >> 10;                         // 0:k 1:v 2:r
                int pm  = (t == 0) ? m : (m - 1);
                float xp   = e0[(size_t)pm * CC + c];
                float coef = (seg == 0) ? e1[c] : (seg == 1) ? e2[c] : e3[c];
                float val  = xp + coef * (v - xp);
                if (seg == 2) val = sigmoidf_(val);
                Cout[(size_t)m * (3 * CC) + n] = val;
            } else if (EPI == 2) {
                int c  = n & (CC - 1);
                int pm = (t == 0) ? (m + TT - 1) : (m - 1);  // wrap shift
                float xp   = e0[(size_t)pm * CC + c];
                float coef = e1[c];
                float val  = xp + coef * (v - xp);
                val = fmaxf(val, 0.0f);
                Cout[(size_t)m * (4 * CC) + n] = val * val;
            } else {
                size_t idx = (size_t)m * CC + n;
                Cout[idx] = e0[idx] + e1[idx] * v;
            }
        }
    }
}

// ---------------- launch ------------------------------------------------------
extern "C" void kernel_launch(void* const* d_in, const int* in_sizes, int n_in,
                              void* d_out, int out_size) {
    const float* x    = (const float*)d_in[0];
    const float* tdec = (const float*)d_in[1];
    const float* tfir = (const float*)d_in[2];
    const float* W_tm = (const float*)d_in[3];
    const float* g1   = (const float*)d_in[4];
    const float* b1   = (const float*)d_in[5];
    const float* tmk  = (const float*)d_in[6];
    const float* tmv  = (const float*)d_in[7];
    const float* tmr  = (const float*)d_in[8];
    const float* W_cm = (const float*)d_in[9];
    const float* W_cp = (const float*)d_in[10];
    const float* g2   = (const float*)d_in[11];
    const float* b2   = (const float*)d_in[12];
    const float* cmk  = (const float*)d_in[13];
    const float* cmr  = (const float*)d_in[14];
    float* out = (float*)d_out;

    float *xn, *kvr, *x1, *xn2, *rr, *hidden;
    cudaGetSymbolAddress((void**)&xn,     g_xn);
    cudaGetSymbolAddress((void**)&kvr,    g_kvr);
    cudaGetSymbolAddress((void**)&x1,     g_x1);
    cudaGetSymbolAddress((void**)&xn2,    g_xn2);
    cudaGetSymbolAddress((void**)&rr,     g_rr);
    cudaGetSymbolAddress((void**)&hidden, g_hidden);

    // 1) LN1
    ln1_kernel<<<MM, 256>>>(x, g1, b1, xn);
    // 2) GEMM1 + time-mix epilogue  (kvr = mix(LN(x) @ W_tm))
    sgemm_kernel<1><<<dim3(3 * CC / 128, MM / 128), 256>>>(
        xn, W_tm, kvr, CC, 3 * CC, x, tmk, tmv, tmr);
    // 3) WKV scan, fused x1 = x + r*y, writes state tail
    wkv_kernel<<<(BB * CC) / 64, 64>>>(kvr, x, tdec, tfir, x1,
                                       out + (size_t)MM * CC);
    // 4) LN2 + rr gate
    ln2_rr_kernel<<<MM, 256>>>(x1, g2, b2, cmr, xn2, rr);
    // 5) GEMM2 + channel-mix relu^2 epilogue (hidden)
    sgemm_kernel<2><<<dim3(4 * CC / 128, MM / 128), 256>>>(
        xn2, W_cm, hidden, CC, 4 * CC, x1, cmk, nullptr, nullptr);
    // 6) GEMM3 + final epilogue (out = x1 + rr*vv)
    sgemm_kernel<3><<<dim3(CC / 128, MM / 128), 256>>>(
        hidden, W_cp, out, 4 * CC, CC, x1, rr, nullptr, nullptr);
}

// round 4
// speedup vs baseline: 2.4978x; 2.4978x over previous
#include <cuda_runtime.h>
#include <cuda_bf16.h>
#include <cstdint>

#define BB 8
#define TT 2048
#define CC 1024
#define MM (BB*TT)          // 16384 rows

// ---------------- scratch (static device arrays; no allocation) -------------
__device__ float g_kvr[(size_t)MM * 3 * CC];
__device__ float g_x1 [(size_t)MM * CC];
__device__ float g_rr [(size_t)MM * CC];
__device__ __nv_bfloat16 g_xn_hi [(size_t)MM * CC];
__device__ __nv_bfloat16 g_xn_lo [(size_t)MM * CC];
__device__ __nv_bfloat16 g_xn2_hi[(size_t)MM * CC];
__device__ __nv_bfloat16 g_xn2_lo[(size_t)MM * CC];
__device__ __nv_bfloat16 g_hid_hi[(size_t)MM * 4 * CC];
__device__ __nv_bfloat16 g_hid_lo[(size_t)MM * 4 * CC];
__device__ __nv_bfloat16 g_wtm_hi[(size_t)3 * CC * CC];   // W_tm^T  [3C, C]
__device__ __nv_bfloat16 g_wtm_lo[(size_t)3 * CC * CC];
__device__ __nv_bfloat16 g_wcm_hi[(size_t)4 * CC * CC];   // W_cm^T  [4C, C]
__device__ __nv_bfloat16 g_wcm_lo[(size_t)4 * CC * CC];
__device__ __nv_bfloat16 g_wcp_hi[(size_t)CC * 4 * CC];   // W_cp^T  [C, 4C]
__device__ __nv_bfloat16 g_wcp_lo[(size_t)CC * 4 * CC];

__device__ __forceinline__ float sigmoidf_(float z) {
    return 1.0f / (1.0f + __expf(-z));
}
__device__ __forceinline__ uint32_t smem_u32(const void* p) {
    uint32_t a;
    asm("{ .reg .u64 t; cvta.to.shared.u64 t, %1; cvt.u32.u64 %0, t; }"
        : "=r"(a) : "l"(p));
    return a;
}
__device__ __forceinline__ void cp16(uint32_t sa, const void* ga) {
    asm volatile("cp.async.cg.shared.global [%0], [%1], 16;"
                 :: "r"(sa), "l"(ga) : "memory");
}
__device__ __forceinline__ void cp_commit() {
    asm volatile("cp.async.commit_group;" ::: "memory");
}
__device__ __forceinline__ void ldx4(uint32_t* r, uint32_t addr) {
    asm volatile("ldmatrix.sync.aligned.m8n8.x4.shared.b16 {%0,%1,%2,%3}, [%4];"
                 : "=r"(r[0]), "=r"(r[1]), "=r"(r[2]), "=r"(r[3]) : "r"(addr));
}
__device__ __forceinline__ void mma16816(float* c, const uint32_t* a,
                                         uint32_t b0, uint32_t b1) {
    asm volatile(
        "mma.sync.aligned.m16n8k16.row.col.f32.bf16.bf16.f32 "
        "{%0,%1,%2,%3}, {%4,%5,%6,%7}, {%8,%9}, {%0,%1,%2,%3};"
        : "+f"(c[0]), "+f"(c[1]), "+f"(c[2]), "+f"(c[3])
        : "r"(a[0]), "r"(a[1]), "r"(a[2]), "r"(a[3]), "r"(b0), "r"(b1));
}

// ---------------- weight transpose + bf16 split ------------------------------
__global__ void transpose_split(const float* __restrict__ W,
                                __nv_bfloat16* __restrict__ Th,
                                __nv_bfloat16* __restrict__ Tl,
                                int K, int N) {
    __shared__ float tile[32][33];
    int n0 = blockIdx.x * 32, k0 = blockIdx.y * 32;
    int tx = threadIdx.x, ty = threadIdx.y;  // 32 x 8
    #pragma unroll
    for (int i = 0; i < 32; i += 8)
        tile[ty + i][tx] = W[(size_t)(k0 + ty + i) * N + n0 + tx];
    __syncthreads();
    #pragma unroll
    for (int i = 0; i < 32; i += 8) {
        float v = tile[tx][ty + i];
        __nv_bfloat16 h = __float2bfloat16(v);
        float l = v - __bfloat162float(h);
        size_t o = (size_t)(n0 + ty + i) * K + k0 + tx;
        Th[o] = h;
        Tl[o] = __float2bfloat16(l);
    }
}

// ---------------- LayerNorm 1 -> bf16 split ----------------------------------
__global__ void ln1_kernel(const float* __restrict__ x,
                           const float* __restrict__ g,
                           const float* __restrict__ b,
                           __nv_bfloat16* __restrict__ oh,
                           __nv_bfloat16* __restrict__ ol) {
    int row = blockIdx.x;
    float4 v = ((const float4*)(x + (size_t)row * CC))[threadIdx.x];
    float s = v.x + v.y + v.z + v.w;
    float q = v.x*v.x + v.y*v.y + v.z*v.z + v.w*v.w;
    int lane = threadIdx.x & 31, wid = threadIdx.x >> 5;
    #pragma unroll
    for (int o = 16; o; o >>= 1) {
        s += __shfl_xor_sync(0xffffffffu, s, o);
        q += __shfl_xor_sync(0xffffffffu, q, o);
    }
    __shared__ float s_s[8], s_q[8];
    if (!lane) { s_s[wid] = s; s_q[wid] = q; }
    __syncthreads();
    if (threadIdx.x == 0) {
        float a = 0.f, c2 = 0.f;
        #pragma unroll
        for (int i = 0; i < 8; i++) { a += s_s[i]; c2 += s_q[i]; }
        s_s[0] = a; s_q[0] = c2;
    }
    __syncthreads();
    float mean = s_s[0] * (1.0f / CC);
    float var  = s_q[0] * (1.0f / CC) - mean * mean;
    float rstd = rsqrtf(var + 1e-5f);
    float4 gv = ((const float4*)g)[threadIdx.x];
    float4 bv = ((const float4*)b)[threadIdx.x];
    float o0 = (v.x - mean) * rstd * gv.x + bv.x;
    float o1 = (v.y - mean) * rstd * gv.y + bv.y;
    float o2 = (v.z - mean) * rstd * gv.z + bv.z;
    float o3 = (v.w - mean) * rstd * gv.w + bv.w;
    __nv_bfloat162 h01 = __floats2bfloat162_rn(o0, o1);
    __nv_bfloat162 h23 = __floats2bfloat162_rn(o2, o3);
    __nv_bfloat162 l01 = __floats2bfloat162_rn(o0 - __low2float(h01), o1 - __high2float(h01));
    __nv_bfloat162 l23 = __floats2bfloat162_rn(o2 - __low2float(h23), o3 - __high2float(h23));
    __nv_bfloat162* ph = (__nv_bfloat162*)(oh + (size_t)row * CC);
    __nv_bfloat162* pl = (__nv_bfloat162*)(ol + (size_t)row * CC);
    ph[threadIdx.x * 2] = h01;  ph[threadIdx.x * 2 + 1] = h23;
    pl[threadIdx.x * 2] = l01;  pl[threadIdx.x * 2 + 1] = l23;
}

// ---------------- LayerNorm 2 + rr gate -> bf16 split ------------------------
__global__ void ln2_rr_kernel(const float* __restrict__ x1,
                              const float* __restrict__ g,
                              const float* __restrict__ b,
                              const float* __restrict__ cmr,
                              __nv_bfloat16* __restrict__ oh,
                              __nv_bfloat16* __restrict__ ol,
                              float* __restrict__ rr) {
    int row = blockIdx.x;
    float4 v = ((const float4*)(x1 + (size_t)row * CC))[threadIdx.x];
    float s = v.x + v.y + v.z + v.w;
    float q = v.x*v.x + v.y*v.y + v.z*v.z + v.w*v.w;
    int lane = threadIdx.x & 31, wid = threadIdx.x >> 5;
    #pragma unroll
    for (int o = 16; o; o >>= 1) {
        s += __shfl_xor_sync(0xffffffffu, s, o);
        q += __shfl_xor_sync(0xffffffffu, q, o);
    }
    __shared__ float s_s[8], s_q[8];
    if (!lane) { s_s[wid] = s; s_q[wid] = q; }
    __syncthreads();
    if (threadIdx.x == 0) {
        float a = 0.f, c2 = 0.f;
        #pragma unroll
        for (int i = 0; i < 8; i++) { a += s_s[i]; c2 += s_q[i]; }
        s_s[0] = a; s_q[0] = c2;
    }
    __syncthreads();
    float mean = s_s[0] * (1.0f / CC);
    float var  = s_q[0] * (1.0f / CC) - mean * mean;
    float rstd = rsqrtf(var + 1e-5f);
    float4 gv = ((const float4*)g)[threadIdx.x];
    float4 bv = ((const float4*)b)[threadIdx.x];
    float o0 = (v.x - mean) * rstd * gv.x + bv.x;
    float o1 = (v.y - mean) * rstd * gv.y + bv.y;
    float o2 = (v.z - mean) * rstd * gv.z + bv.z;
    float o3 = (v.w - mean) * rstd * gv.w + bv.w;
    __nv_bfloat162 h01 = __floats2bfloat162_rn(o0, o1);
    __nv_bfloat162 h23 = __floats2bfloat162_rn(o2, o3);
    __nv_bfloat162 l01 = __floats2bfloat162_rn(o0 - __low2float(h01), o1 - __high2float(h01));
    __nv_bfloat162 l23 = __floats2bfloat162_rn(o2 - __low2float(h23), o3 - __high2float(h23));
    __nv_bfloat162* ph = (__nv_bfloat162*)(oh + (size_t)row * CC);
    __nv_bfloat162* pl = (__nv_bfloat162*)(ol + (size_t)row * CC);
    ph[threadIdx.x * 2] = h01;  ph[threadIdx.x * 2 + 1] = h23;
    pl[threadIdx.x * 2] = l01;  pl[threadIdx.x * 2 + 1] = l23;

    int t = row & (TT - 1);
    int prow = (t == 0) ? (row + TT - 1) : (row - 1);
    float4 xp = ((const float4*)(x1 + (size_t)prow * CC))[threadIdx.x];
    float4 cr = ((const float4*)cmr)[threadIdx.x];
    float4 r4;
    r4.x = sigmoidf_(xp.x + cr.x * (o0 - xp.x));
    r4.y = sigmoidf_(xp.y + cr.y * (o1 - xp.y));
    r4.z = sigmoidf_(xp.z + cr.z * (o2 - xp.z));
    r4.w = sigmoidf_(xp.w + cr.w * (o3 - xp.w));
    ((float4*)(rr + (size_t)row * CC))[threadIdx.x] = r4;
}

// ---------------- WKV scan (fused x1 = x + r*y) ------------------------------
#define PF 8
__global__ void wkv_kernel(const float* __restrict__ kvr,
                           const float* __restrict__ x,
                           const float* __restrict__ wd,
                           const float* __restrict__ uf,
                           float* __restrict__ x1,
                           float* __restrict__ out_state) {
    int gid = blockIdx.x * blockDim.x + threadIdx.x;
    int b = gid >> 10, c = gid & (CC - 1);
    float w = wd[c], u = uf[c];
    float aa = 0.0f, bb = -1e38f;
    size_t kbase = (size_t)b * TT * (3 * CC) + c;
    size_t xbase = (size_t)b * TT * CC + c;

    float pk[PF], pv[PF], pr[PF], px[PF];
    #pragma unroll
    for (int i = 0; i < PF; i++) {
        size_t ko = kbase + (size_t)i * (3 * CC);
        pk[i] = kvr[ko];  pv[i] = kvr[ko + CC];  pr[i] = kvr[ko + 2 * CC];
        px[i] = x[xbase + (size_t)i * CC];
    }
    for (int t0 = 0; t0 < TT; t0 += PF) {
        #pragma unroll
        for (int i = 0; i < PF; i++) {
            int t = t0 + i;
            float kk = pk[i], vv = pv[i], r = pr[i], xv = px[i];
            int tn = t + PF;
            if (tn < TT) {
                size_t ko = kbase + (size_t)tn * (3 * CC);
                pk[i] = kvr[ko];  pv[i] = kvr[ko + CC];  pr[i] = kvr[ko + 2 * CC];
                px[i] = x[xbase + (size_t)tn * CC];
            }
            float ww = u + kk;
            float p  = fmaxf(bb, ww);
            float e1 = __expf(bb - p);
            float e2 = __expf(ww - p);
            float y  = __fdividef(e1 * aa + e2 * vv, e1 + e2 + 1e-8f);
            x1[xbase + (size_t)t * CC] = xv + r * y;
            float w2 = w + bb;
            float p2 = fmaxf(w2, kk);
            float ea = __expf(w2 - p2);
            float eb = __expf(kk - p2);
            aa = ea * aa + eb * vv;
            bb = p2 + __logf(ea + eb + 1e-8f);
        }
    }
    out_state[(size_t)gid * 2 + 0] = aa;
    out_state[(size_t)gid * 2 + 1] = bb;
}

// ---------------- HMMA GEMM: C[128,128] = A[128,K] @ B[128,K]^T --------------
// bf16x3 compensated: C = Ah*Bh + Ah*Bl + Al*Bh, fp32 accumulate.
// cp.async 3-stage pipeline, BK=64, 128B swizzled smem rows, ldmatrix feeds.
#define BKG 64
#define STAGES 3
#define STG_BYTES 65536            // Ah|Al|Bh|Bl, each 128x64 bf16 = 16KB
#define GSMEM (STAGES * STG_BYTES)

template <int EPI>
__global__ void __launch_bounds__(256, 1)
mma_gemm(const __nv_bfloat16* __restrict__ Ah, const __nv_bfloat16* __restrict__ Al,
         const __nv_bfloat16* __restrict__ Bh, const __nv_bfloat16* __restrict__ Bl,
         int K,
         float* __restrict__ outf,
         __nv_bfloat16* __restrict__ outh, __nv_bfloat16* __restrict__ outl,
         const float* __restrict__ e0, const float* __restrict__ e1,
         const float* __restrict__ e2, const float* __restrict__ e3) {
    extern __shared__ char smem[];
    const int tid = threadIdx.x;
    const int m0 = blockIdx.y * 128;
    const int n0 = blockIdx.x * 128;
    uint32_t sb = smem_u32(smem);
    const int warp = tid >> 5, lane = tid & 31;
    const int wm = warp & 1, wn = warp >> 1;   // warp tile: 64(m) x 32(n)

    float acc[4][4][4];
    #pragma unroll
    for (int i = 0; i < 4; i++)
        #pragma unroll
        for (int j = 0; j < 4; j++)
            #pragma unroll
            for (int e = 0; e < 4; e++) acc[i][j][e] = 0.f;

    const __nv_bfloat16* gb[4] = {
        Ah + (size_t)m0 * K, Al + (size_t)m0 * K,
        Bh + (size_t)n0 * K, Bl + (size_t)n0 * K };
    const int crow = tid >> 3;            // helper: row fragment of copy
    const int ccol = tid & 7;             // 16B chunk 0..7

    auto copy_stage = [&](int ks, int buf) {
        int k0 = ks * BKG;
        #pragma unroll
        for (int i = 0; i < 16; i++) {
            int blk = i >> 2;
            int row = (i & 3) * 32 + crow;
            uint32_t sa = sb + (uint32_t)buf * STG_BYTES + (uint32_t)blk * 16384
                        + (uint32_t)row * 128 + (uint32_t)((ccol ^ (row & 7)) << 4);
            cp16(sa, gb[blk] + (size_t)row * K + k0 + ccol * 8);
        }
        cp_commit();
    };

    copy_stage(0, 0);
    copy_stage(1, 1);

    const int NK = K / BKG;
    for (int ks = 0; ks < NK; ks++) {
        asm volatile("cp.async.wait_group 1;" ::: "memory");
        __syncthreads();
        if (ks + STAGES - 1 < NK) copy_stage(ks + STAGES - 1, (ks + STAGES - 1) % STAGES);
        else cp_commit();   // keep group count uniform so wait_group 1 => current ready

        uint32_t bufb = sb + (uint32_t)(ks % STAGES) * STG_BYTES;
        #pragma unroll
        for (int kk = 0; kk < 4; kk++) {      // four k16 steps per BK=64
            uint32_t ah[4][4], al[4][4];
            #pragma unroll
            for (int mi = 0; mi < 4; mi++) {
                int row = wm * 64 + mi * 16 + (lane & 15);
                int ch  = kk * 2 + (lane >> 4);
                uint32_t off = (uint32_t)row * 128 + (uint32_t)((ch ^ (row & 7)) << 4);
                ldx4(ah[mi], bufb + off);
                ldx4(al[mi], bufb + 16384 + off);
            }
            uint32_t tbh0[4], tbl0[4], tbh1[4], tbl1[4];
            {
                int row = wn * 32 + (lane & 15);
                int ch  = kk * 2 + (lane >> 4);
                uint32_t off = (uint32_t)row * 128 + (uint32_t)((ch ^ (row & 7)) << 4);
                ldx4(tbh0, bufb + 32768 + off);
                ldx4(tbl0, bufb + 49152 + off);
                int row2 = row + 16;
                uint32_t off2 = (uint32_t)row2 * 128 + (uint32_t)((ch ^ (row2 & 7)) << 4);
                ldx4(tbh1, bufb + 32768 + off2);
                ldx4(tbl1, bufb + 49152 + off2);
            }
            uint32_t bh[4][2] = {{tbh0[0],tbh0[2]},{tbh0[1],tbh0[3]},
                                 {tbh1[0],tbh1[2]},{tbh1[1],tbh1[3]}};
            uint32_t bl[4][2] = {{tbl0[0],tbl0[2]},{tbl0[1],tbl0[3]},
                                 {tbl1[0],tbl1[2]},{tbl1[1],tbl1[3]}};
            #pragma unroll
            for (int mi = 0; mi < 4; mi++)
                #pragma unroll
                for (int nj = 0; nj < 4; nj++) {
                    mma16816(acc[mi][nj], ah[mi], bh[nj][0], bh[nj][1]);
                    mma16816(acc[mi][nj], ah[mi], bl[nj][0], bl[nj][1]);
                    mma16816(acc[mi][nj], al[mi], bh[nj][0], bh[nj][1]);
                }
        }
    }

    // ---------------- fused epilogue -----------------------------------------
    const int qr = lane >> 2;        // 0..7
    const int qe = lane & 3;         // 0..3
    #pragma unroll
    for (int mi = 0; mi < 4; mi++) {
        #pragma unroll
        for (int rh = 0; rh < 2; rh++) {
            int m = m0 + wm * 64 + mi * 16 + qr + rh * 8;
            int t = m & (TT - 1);
            if (EPI == 1) {
                int seg = n0 >> 10;
                const float* coefp = (seg == 0) ? e1 : (seg == 1) ? e2 : e3;
                int pm = t ? (m - 1) : m;
                const float* xpr = e0 + (size_t)pm * CC;
                float* orow = outf + (size_t)m * (3 * CC);
                #pragma unroll
                for (int nj = 0; nj < 4; nj++) {
                    int n = n0 + wn * 32 + nj * 8 + 2 * qe;
                    int c = n & (CC - 1);
                    float v0 = acc[mi][nj][rh * 2 + 0];
                    float v1 = acc[mi][nj][rh * 2 + 1];
                    float x0 = xpr[c], x1v = xpr[c + 1];
                    float a0 = x0 + coefp[c]     * (v0 - x0);
                    float a1 = x1v + coefp[c + 1] * (v1 - x1v);
                    if (seg == 2) { a0 = sigmoidf_(a0); a1 = sigmoidf_(a1); }
                    float2 o = {a0, a1};
                    *(float2*)(orow + n) = o;
                }
            } else if (EPI == 2) {
                int pm = t ? (m - 1) : (m + TT - 1);
                const float* xpr = e0 + (size_t)pm * CC;
                size_t rowo = (size_t)m * (4 * CC);
                #pragma unroll
                for (int nj = 0; nj < 4; nj++) {
                    int n = n0 + wn * 32 + nj * 8 + 2 * qe;
                    int c = n & (CC - 1);
                    float v0 = acc[mi][nj][rh * 2 + 0];
                    float v1 = acc[mi][nj][rh * 2 + 1];
                    float x0 = xpr[c], x1v = xpr[c + 1];
                    float a0 = fmaxf(x0 + e1[c]     * (v0 - x0), 0.f);
                    float a1 = fmaxf(x1v + e1[c + 1] * (v1 - x1v), 0.f);
                    a0 *= a0; a1 *= a1;
                    __nv_bfloat162 h = __floats2bfloat162_rn(a0, a1);
                    __nv_bfloat162 l = __floats2bfloat162_rn(
                        a0 - __low2float(h), a1 - __high2float(h));
                    *(__nv_bfloat162*)(outh + rowo + n) = h;
                    *(__nv_bfloat162*)(outl + rowo + n) = l;
                }
            } else {
                size_t rowo = (size_t)m * CC;
                #pragma unroll
                for (int nj = 0; nj < 4; nj++) {
                    int n = n0 + wn * 32 + nj * 8 + 2 * qe;
                    float2 xv = *(const float2*)(e0 + rowo + n);
                    float2 rv = *(const float2*)(e1 + rowo + n);
                    float2 o;
                    o.x = xv.x + rv.x * acc[mi][nj][rh * 2 + 0];
                    o.y = xv.y + rv.y * acc[mi][nj][rh * 2 + 1];
                    *(float2*)(outf + rowo + n) = o;
                }
            }
        }
    }
}

// ---------------- launch ------------------------------------------------------
extern "C" void kernel_launch(void* const* d_in, const int* in_sizes, int n_in,
                              void* d_out, int out_size) {
    const float* x    = (const float*)d_in[0];
    const float* tdec = (const float*)d_in[1];
    const float* tfir = (const float*)d_in[2];
    const float* W_tm = (const float*)d_in[3];
    const float* g1   = (const float*)d_in[4];
    const float* b1   = (const float*)d_in[5];
    const float* tmk  = (const float*)d_in[6];
    const float* tmv  = (const float*)d_in[7];
    const float* tmr  = (const float*)d_in[8];
    const float* W_cm = (const float*)d_in[9];
    const float* W_cp = (const float*)d_in[10];
    const float* g2   = (const float*)d_in[11];
    const float* b2   = (const float*)d_in[12];
    const float* cmk  = (const float*)d_in[13];
    const float* cmr  = (const float*)d_in[14];
    float* out = (float*)d_out;

    float *kvr, *x1, *rr;
    __nv_bfloat16 *xnh, *xnl, *xn2h, *xn2l, *hidh, *hidl;
    __nv_bfloat16 *wtmh, *wtml, *wcmh, *wcml, *wcph, *wcpl;
    cudaGetSymbolAddress((void**)&kvr,  g_kvr);
    cudaGetSymbolAddress((void**)&x1,   g_x1);
    cudaGetSymbolAddress((void**)&rr,   g_rr);
    cudaGetSymbolAddress((void**)&xnh,  g_xn_hi);
    cudaGetSymbolAddress((void**)&xnl,  g_xn_lo);
    cudaGetSymbolAddress((void**)&xn2h, g_xn2_hi);
    cudaGetSymbolAddress((void**)&xn2l, g_xn2_lo);
    cudaGetSymbolAddress((void**)&hidh, g_hid_hi);
    cudaGetSymbolAddress((void**)&hidl, g_hid_lo);
    cudaGetSymbolAddress((void**)&wtmh, g_wtm_hi);
    cudaGetSymbolAddress((void**)&wtml, g_wtm_lo);
    cudaGetSymbolAddress((void**)&wcmh, g_wcm_hi);
    cudaGetSymbolAddress((void**)&wcml, g_wcm_lo);
    cudaGetSymbolAddress((void**)&wcph, g_wcp_hi);
    cudaGetSymbolAddress((void**)&wcpl, g_wcp_lo);

    cudaFuncSetAttribute(mma_gemm<1>, cudaFuncAttributeMaxDynamicSharedMemorySize, GSMEM);
    cudaFuncSetAttribute(mma_gemm<2>, cudaFuncAttributeMaxDynamicSharedMemorySize, GSMEM);
    cudaFuncSetAttribute(mma_gemm<3>, cudaFuncAttributeMaxDynamicSharedMemorySize, GSMEM);

    dim3 tb(32, 8);
    transpose_split<<<dim3(3*CC/32, CC/32), tb>>>(W_tm, wtmh, wtml, CC, 3*CC);
    transpose_split<<<dim3(4*CC/32, CC/32), tb>>>(W_cm, wcmh, wcml, CC, 4*CC);
    transpose_split<<<dim3(CC/32, 4*CC/32), tb>>>(W_cp, wcph, wcpl, 4*CC, CC);

    // 1) LN1 -> bf16 split
    ln1_kernel<<<MM, 256>>>(x, g1, b1, xnh, xnl);
    // 2) GEMM1 + time-mix epilogue -> kvr (fp32)
    mma_gemm<1><<<dim3(3*CC/128, MM/128), 256, GSMEM>>>(
        xnh, xnl, wtmh, wtml, CC, kvr, nullptr, nullptr, x, tmk, tmv, tmr);
    // 3) WKV scan -> x1, state tail of out
    wkv_kernel<<<(BB*CC)/64, 64>>>(kvr, x, tdec, tfir, x1, out + (size_t)MM * CC);
    // 4) LN2 + rr gate -> bf16 split + rr
    ln2_rr_kernel<<<MM, 256>>>(x1, g2, b2, cmr, xn2h, xn2l, rr);
    // 5) GEMM2 + channel-mix relu^2 epilogue -> hidden bf16 split
    mma_gemm<2><<<dim3(4*CC/128, MM/128), 256, GSMEM>>>(
        xn2h, xn2l, wcmh, wcml, CC, nullptr, hidh, hidl, x1, cmk, nullptr, nullptr);
    // 6) GEMM3 + final epilogue -> out = x1 + rr*vv
    mma_gemm<3><<<dim3(CC/128, MM/128), 256, GSMEM>>>(
        hidh, hidl, wcph, wcpl, 4*CC, out, nullptr, nullptr, x1, rr, nullptr, nullptr);
}

// round 6
// speedup vs baseline: 3.5497x; 1.4211x over previous
#include <cuda_runtime.h>
#include <cuda_fp16.h>
#include <cuda_bf16.h>
#include <cstdint>

#define BB 8
#define TT 2048
#define CC 1024
#define MM (BB*TT)          // 16384 rows

// ---------------- scratch (static device arrays; no allocation) -------------
__device__ float g_kvr[(size_t)MM * 3 * CC];
__device__ float g_x1 [(size_t)MM * CC];
__device__ float g_rr [(size_t)MM * CC];
__device__ __half g_xn  [(size_t)MM * CC];
__device__ __half g_xn2 [(size_t)MM * CC];
__device__ __half g_hid [(size_t)MM * 4 * CC];
__device__ __half g_wtm [(size_t)3 * CC * CC];   // W_tm^T  [3C, C]
__device__ __half g_wcm [(size_t)4 * CC * CC];   // W_cm^T  [4C, C]
__device__ __half g_wcp [(size_t)CC * 4 * CC];   // W_cp^T  [C, 4C]

__device__ __forceinline__ float sigmoidf_(float z) {
    return 1.0f / (1.0f + __expf(-z));
}
__device__ __forceinline__ uint32_t smem_u32(const void* p) {
    uint32_t a;
    asm("{ .reg .u64 t; cvta.to.shared.u64 t, %1; cvt.u32.u64 %0, t; }"
        : "=r"(a) : "l"(p));
    return a;
}
__device__ __forceinline__ void cp16(uint32_t sa, const void* ga) {
    asm volatile("cp.async.cg.shared.global [%0], [%1], 16;"
                 :: "r"(sa), "l"(ga) : "memory");
}
__device__ __forceinline__ void cp_commit() {
    asm volatile("cp.async.commit_group;" ::: "memory");
}
__device__ __forceinline__ void ldx4(uint32_t* r, uint32_t addr) {
    asm volatile("ldmatrix.sync.aligned.m8n8.x4.shared.b16 {%0,%1,%2,%3}, [%4];"
                 : "=r"(r[0]), "=r"(r[1]), "=r"(r[2]), "=r"(r[3]) : "r"(addr));
}
__device__ __forceinline__ void mma16816(float* c, const uint32_t* a,
                                         uint32_t b0, uint32_t b1) {
    asm volatile(
        "mma.sync.aligned.m16n8k16.row.col.f32.f16.f16.f32 "
        "{%0,%1,%2,%3}, {%4,%5,%6,%7}, {%8,%9}, {%0,%1,%2,%3};"
        : "+f"(c[0]), "+f"(c[1]), "+f"(c[2]), "+f"(c[3])
        : "r"(a[0]), "r"(a[1]), "r"(a[2]), "r"(a[3]), "r"(b0), "r"(b1));
}

// ---------------- weight transpose -> fp16 -----------------------------------
__global__ void transpose_h(const float* __restrict__ W,
                            __half* __restrict__ Th, int K, int N) {
    __shared__ float tile[32][33];
    int n0 = blockIdx.x * 32, k0 = blockIdx.y * 32;
    int tx = threadIdx.x, ty = threadIdx.y;  // 32 x 8
    #pragma unroll
    for (int i = 0; i < 32; i += 8)
        tile[ty + i][tx] = W[(size_t)(k0 + ty + i) * N + n0 + tx];
    __syncthreads();
    #pragma unroll
    for (int i = 0; i < 32; i += 8)
        Th[(size_t)(n0 + ty + i) * K + k0 + tx] = __float2half_rn(tile[tx][ty + i]);
}

// ---------------- LayerNorm 1 -> fp16 ----------------------------------------
__global__ void ln1_kernel(const float* __restrict__ x,
                           const float* __restrict__ g,
                           const float* __restrict__ b,
                           __half* __restrict__ oh) {
    int row = blockIdx.x;
    float4 v = ((const float4*)(x + (size_t)row * CC))[threadIdx.x];
    float s = v.x + v.y + v.z + v.w;
    float q = v.x*v.x + v.y*v.y + v.z*v.z + v.w*v.w;
    int lane = threadIdx.x & 31, wid = threadIdx.x >> 5;
    #pragma unroll
    for (int o = 16; o; o >>= 1) {
        s += __shfl_xor_sync(0xffffffffu, s, o);
        q += __shfl_xor_sync(0xffffffffu, q, o);
    }
    __shared__ float s_s[8], s_q[8];
    if (!lane) { s_s[wid] = s; s_q[wid] = q; }
    __syncthreads();
    if (threadIdx.x == 0) {
        float a = 0.f, c2 = 0.f;
        #pragma unroll
        for (int i = 0; i < 8; i++) { a += s_s[i]; c2 += s_q[i]; }
        s_s[0] = a; s_q[0] = c2;
    }
    __syncthreads();
    float mean = s_s[0] * (1.0f / CC);
    float var  = s_q[0] * (1.0f / CC) - mean * mean;
    float rstd = rsqrtf(var + 1e-5f);
    float4 gv = ((const float4*)g)[threadIdx.x];
    float4 bv = ((const float4*)b)[threadIdx.x];
    __half2 h01 = __floats2half2_rn((v.x - mean) * rstd * gv.x + bv.x,
                                    (v.y - mean) * rstd * gv.y + bv.y);
    __half2 h23 = __floats2half2_rn((v.z - mean) * rstd * gv.z + bv.z,
                                    (v.w - mean) * rstd * gv.w + bv.w);
    __half2* ph = (__half2*)(oh + (size_t)row * CC);
    ph[threadIdx.x * 2] = h01;  ph[threadIdx.x * 2 + 1] = h23;
}

// ---------------- LayerNorm 2 + rr gate -> fp16 ------------------------------
__global__ void ln2_rr_kernel(const float* __restrict__ x1,
                              const float* __restrict__ g,
                              const float* __restrict__ b,
                              const float* __restrict__ cmr,
                              __half* __restrict__ oh,
                              float* __restrict__ rr) {
    int row = blockIdx.x;
    float4 v = ((const float4*)(x1 + (size_t)row * CC))[threadIdx.x];
    float s = v.x + v.y + v.z + v.w;
    float q = v.x*v.x + v.y*v.y + v.z*v.z + v.w*v.w;
    int lane = threadIdx.x & 31, wid = threadIdx.x >> 5;
    #pragma unroll
    for (int o = 16; o; o >>= 1) {
        s += __shfl_xor_sync(0xffffffffu, s, o);
        q += __shfl_xor_sync(0xffffffffu, q, o);
    }
    __shared__ float s_s[8], s_q[8];
    if (!lane) { s_s[wid] = s; s_q[wid] = q; }
    __syncthreads();
    if (threadIdx.x == 0) {
        float a = 0.f, c2 = 0.f;
        #pragma unroll
        for (int i = 0; i < 8; i++) { a += s_s[i]; c2 += s_q[i]; }
        s_s[0] = a; s_q[0] = c2;
    }
    __syncthreads();
    float mean = s_s[0] * (1.0f / CC);
    float var  = s_q[0] * (1.0f / CC) - mean * mean;
    float rstd = rsqrtf(var + 1e-5f);
    float4 gv = ((const float4*)g)[threadIdx.x];
    float4 bv = ((const float4*)b)[threadIdx.x];
    float o0 = (v.x - mean) * rstd * gv.x + bv.x;
    float o1 = (v.y - mean) * rstd * gv.y + bv.y;
    float o2 = (v.z - mean) * rstd * gv.z + bv.z;
    float o3 = (v.w - mean) * rstd * gv.w + bv.w;
    __half2* ph = (__half2*)(oh + (size_t)row * CC);
    ph[threadIdx.x * 2]     = __floats2half2_rn(o0, o1);
    ph[threadIdx.x * 2 + 1] = __floats2half2_rn(o2, o3);

    int t = row & (TT - 1);
    int prow = (t == 0) ? (row + TT - 1) : (row - 1);
    float4 xp = ((const float4*)(x1 + (size_t)prow * CC))[threadIdx.x];
    float4 cr = ((const float4*)cmr)[threadIdx.x];
    float4 r4;
    r4.x = sigmoidf_(xp.x + cr.x * (o0 - xp.x));
    r4.y = sigmoidf_(xp.y + cr.y * (o1 - xp.y));
    r4.z = sigmoidf_(xp.z + cr.z * (o2 - xp.z));
    r4.w = sigmoidf_(xp.w + cr.w * (o3 - xp.w));
    ((float4*)(rr + (size_t)row * CC))[threadIdx.x] = r4;
}

// ---------------- WKV scan (fused x1 = x + r*y) ------------------------------
#define PF 8
__global__ void wkv_kernel(const float* __restrict__ kvr,
                           const float* __restrict__ x,
                           const float* __restrict__ wd,
                           const float* __restrict__ uf,
                           float* __restrict__ x1,
                           float* __restrict__ out_state) {
    int gid = blockIdx.x * blockDim.x + threadIdx.x;
    int b = gid >> 10, c = gid & (CC - 1);
    float w = wd[c], u = uf[c];
    float aa = 0.0f, bb = -1e38f;
    size_t kbase = (size_t)b * TT * (3 * CC) + c;
    size_t xbase = (size_t)b * TT * CC + c;

    float pk[PF], pv[PF], pr[PF], px[PF];
    #pragma unroll
    for (int i = 0; i < PF; i++) {
        size_t ko = kbase + (size_t)i * (3 * CC);
        pk[i] = kvr[ko];  pv[i] = kvr[ko + CC];  pr[i] = kvr[ko + 2 * CC];
        px[i] = x[xbase + (size_t)i * CC];
    }
    for (int t0 = 0; t0 < TT; t0 += PF) {
        #pragma unroll
        for (int i = 0; i < PF; i++) {
            int t = t0 + i;
            float kk = pk[i], vv = pv[i], r = pr[i], xv = px[i];
            int tn = t + PF;
            if (tn < TT) {
                size_t ko = kbase + (size_t)tn * (3 * CC);
                pk[i] = kvr[ko];  pv[i] = kvr[ko + CC];  pr[i] = kvr[ko + 2 * CC];
                px[i] = x[xbase + (size_t)tn * CC];
            }
            float ww = u + kk;
            float p  = fmaxf(bb, ww);
            float e1 = __expf(bb - p);
            float e2 = __expf(ww - p);
            float y  = __fdividef(e1 * aa + e2 * vv, e1 + e2 + 1e-8f);
            x1[xbase + (size_t)t * CC] = xv + r * y;
            float w2 = w + bb;
            float p2 = fmaxf(w2, kk);
            float ea = __expf(w2 - p2);
            float eb = __expf(kk - p2);
            aa = ea * aa + eb * vv;
            bb = p2 + __logf(ea + eb + 1e-8f);
        }
    }
    out_state[(size_t)gid * 2 + 0] = aa;
    out_state[(size_t)gid * 2 + 1] = bb;
}

// ---------------- HMMA GEMM: C[256,128] = A[256,K] @ B[128,K]^T --------------
// Single-product fp16, fp32 accumulate. cp.async 3-stage, BK=64, swizzled rows.
// 512 threads = 16 warps, warp tile 64x32 (wm=warp>>2, wn=warp&3).
#define BKG 64
#define STAGES 3
#define STG_BYTES 49152            // A 256x64x2 = 32KB | B 128x64x2 = 16KB
#define GSMEM (STAGES * STG_BYTES)

template <int EPI>
__global__ void __launch_bounds__(512, 1)
mma_gemm(const __half* __restrict__ A, const __half* __restrict__ B,
         int K,
         float* __restrict__ outf, __half* __restrict__ outh,
         const float* __restrict__ e0, const float* __restrict__ e1,
         const float* __restrict__ e2, const float* __restrict__ e3) {
    extern __shared__ char smem[];
    const int tid = threadIdx.x;
    const int m0 = blockIdx.y * 256;
    const int n0 = blockIdx.x * 128;
    uint32_t sb = smem_u32(smem);
    const int warp = tid >> 5, lane = tid & 31;
    const int wm = warp >> 2, wn = warp & 3;   // warp tile: 64(m) x 32(n)

    float acc[4][4][4];
    #pragma unroll
    for (int i = 0; i < 4; i++)
        #pragma unroll
        for (int j = 0; j < 4; j++)
            #pragma unroll
            for (int e = 0; e < 4; e++) acc[i][j][e] = 0.f;

    const __half* Ab = A + (size_t)m0 * K;
    const __half* Bb = B + (size_t)n0 * K;
    const int crow = tid >> 3;            // 0..63
    const int ccol = tid & 7;             // 16B chunk 0..7

    auto copy_stage = [&](int ks, int buf) {
        int k0 = ks * BKG;
        uint32_t base = sb + (uint32_t)buf * STG_BYTES;
        #pragma unroll
        for (int i = 0; i < 4; i++) {     // A: 256 rows
            int row = i * 64 + crow;
            uint32_t sa = base + (uint32_t)row * 128 + (uint32_t)((ccol ^ (row & 7)) << 4);
            cp16(sa, Ab + (size_t)row * K + k0 + ccol * 8);
        }
        #pragma unroll
        for (int i = 0; i < 2; i++) {     // B: 128 rows
            int row = i * 64 + crow;
            uint32_t sa = base + 32768 + (uint32_t)row * 128 + (uint32_t)((ccol ^ (row & 7)) << 4);
            cp16(sa, Bb + (size_t)row * K + k0 + ccol * 8);
        }
        cp_commit();
    };

    copy_stage(0, 0);
    copy_stage(1, 1);

    const int NK = K / BKG;
    for (int ks = 0; ks < NK; ks++) {
        asm volatile("cp.async.wait_group 1;" ::: "memory");
        __syncthreads();
        if (ks + STAGES - 1 < NK) copy_stage(ks + STAGES - 1, (ks + STAGES - 1) % STAGES);
        else cp_commit();   // uniform group count: wait_group 1 => current ready

        uint32_t bufb = sb + (uint32_t)(ks % STAGES) * STG_BYTES;
        #pragma unroll
        for (int kk = 0; kk < 4; kk++) {
            uint32_t ah[4][4];
            #pragma unroll
            for (int mi = 0; mi < 4; mi++) {
                int row = wm * 64 + mi * 16 + (lane & 15);
                int ch  = kk * 2 + (lane >> 4);
                uint32_t off = (uint32_t)row * 128 + (uint32_t)((ch ^ (row & 7)) << 4);
                ldx4(ah[mi], bufb + off);
            }
            uint32_t tb0[4], tb1[4];
            {
                int row = wn * 32 + (lane & 15);
                int ch  = kk * 2 + (lane >> 4);
                uint32_t off = (uint32_t)row * 128 + (uint32_t)((ch ^ (row & 7)) << 4);
                ldx4(tb0, bufb + 32768 + off);
                int row2 = row + 16;
                uint32_t off2 = (uint32_t)row2 * 128 + (uint32_t)((ch ^ (row2 & 7)) << 4);
                ldx4(tb1, bufb + 32768 + off2);
            }
            uint32_t bfr[4][2] = {{tb0[0],tb0[2]},{tb0[1],tb0[3]},
                                  {tb1[0],tb1[2]},{tb1[1],tb1[3]}};
            #pragma unroll
            for (int mi = 0; mi < 4; mi++)
                #pragma unroll
                for (int nj = 0; nj < 4; nj++)
                    mma16816(acc[mi][nj], ah[mi], bfr[nj][0], bfr[nj][1]);
        }
    }

    // ---------------- fused epilogue -----------------------------------------
    const int qr = lane >> 2;        // 0..7
    const int qe = lane & 3;         // 0..3
    #pragma unroll
    for (int mi = 0; mi < 4; mi++) {
        #pragma unroll
        for (int rh = 0; rh < 2; rh++) {
            int m = m0 + wm * 64 + mi * 16 + qr + rh * 8;
            int t = m & (TT - 1);
            if (EPI == 1) {
                int seg = n0 >> 10;
                const float* coefp = (seg == 0) ? e1 : (seg == 1) ? e2 : e3;
                int pm = t ? (m - 1) : m;
                const float* xpr = e0 + (size_t)pm * CC;
                float* orow = outf + (size_t)m * (3 * CC);
                #pragma unroll
                for (int nj = 0; nj < 4; nj++) {
                    int n = n0 + wn * 32 + nj * 8 + 2 * qe;
                    int c = n & (CC - 1);
                    float v0 = acc[mi][nj][rh * 2 + 0];
                    float v1 = acc[mi][nj][rh * 2 + 1];
                    float x0 = xpr[c], x1v = xpr[c + 1];
                    float a0 = x0  + coefp[c]     * (v0 - x0);
                    float a1 = x1v + coefp[c + 1] * (v1 - x1v);
                    if (seg == 2) { a0 = sigmoidf_(a0); a1 = sigmoidf_(a1); }
                    float2 o = {a0, a1};
                    *(float2*)(orow + n) = o;
                }
            } else if (EPI == 2) {
                int pm = t ? (m - 1) : (m + TT - 1);
                const float* xpr = e0 + (size_t)pm * CC;
                size_t rowo = (size_t)m * (4 * CC);
                #pragma unroll
                for (int nj = 0; nj < 4; nj++) {
                    int n = n0 + wn * 32 + nj * 8 + 2 * qe;
                    int c = n & (CC - 1);
                    float v0 = acc[mi][nj][rh * 2 + 0];
                    float v1 = acc[mi][nj][rh * 2 + 1];
                    float x0 = xpr[c], x1v = xpr[c + 1];
                    float a0 = fmaxf(x0  + e1[c]     * (v0 - x0), 0.f);
                    float a1 = fmaxf(x1v + e1[c + 1] * (v1 - x1v), 0.f);
                    *(__half2*)(outh + rowo + n) = __floats2half2_rn(a0 * a0, a1 * a1);
                }
            } else {
                size_t rowo = (size_t)m * CC;
                #pragma unroll
                for (int nj = 0; nj < 4; nj++) {
                    int n = n0 + wn * 32 + nj * 8 + 2 * qe;
                    float2 xv = *(const float2*)(e0 + rowo + n);
                    float2 rv = *(const float2*)(e1 + rowo + n);
                    float2 o;
                    o.x = xv.x + rv.x * acc[mi][nj][rh * 2 + 0];
                    o.y = xv.y + rv.y * acc[mi][nj][rh * 2 + 1];
                    *(float2*)(outf + rowo + n) = o;
                }
            }
        }
    }
}

// ---------------- launch ------------------------------------------------------
extern "C" void kernel_launch(void* const* d_in, const int* in_sizes, int n_in,
                              void* d_out, int out_size) {
    const float* x    = (const float*)d_in[0];
    const float* tdec = (const float*)d_in[1];
    const float* tfir = (const float*)d_in[2];
    const float* W_tm = (const float*)d_in[3];
    const float* g1   = (const float*)d_in[4];
    const float* b1   = (const float*)d_in[5];
    const float* tmk  = (const float*)d_in[6];
    const float* tmv  = (const float*)d_in[7];
    const float* tmr  = (const float*)d_in[8];
    const float* W_cm = (const float*)d_in[9];
    const float* W_cp = (const float*)d_in[10];
    const float* g2   = (const float*)d_in[11];
    const float* b2   = (const float*)d_in[12];
    const float* cmk  = (const float*)d_in[13];
    const float* cmr  = (const float*)d_in[14];
    float* out = (float*)d_out;

    float *kvr, *x1, *rr;
    __half *xn, *xn2, *hid, *wtm, *wcm, *wcp;
    cudaGetSymbolAddress((void**)&kvr, g_kvr);
    cudaGetSymbolAddress((void**)&x1,  g_x1);
    cudaGetSymbolAddress((void**)&rr,  g_rr);
    cudaGetSymbolAddress((void**)&xn,  g_xn);
    cudaGetSymbolAddress((void**)&xn2, g_xn2);
    cudaGetSymbolAddress((void**)&hid, g_hid);
    cudaGetSymbolAddress((void**)&wtm, g_wtm);
    cudaGetSymbolAddress((void**)&wcm, g_wcm);
    cudaGetSymbolAddress((void**)&wcp, g_wcp);

    cudaFuncSetAttribute(mma_gemm<1>, cudaFuncAttributeMaxDynamicSharedMemorySize, GSMEM);
    cudaFuncSetAttribute(mma_gemm<2>, cudaFuncAttributeMaxDynamicSharedMemorySize, GSMEM);
    cudaFuncSetAttribute(mma_gemm<3>, cudaFuncAttributeMaxDynamicSharedMemorySize, GSMEM);

    dim3 tb(32, 8);
    transpose_h<<<dim3(3*CC/32, CC/32), tb>>>(W_tm, wtm, CC, 3*CC);
    transpose_h<<<dim3(4*CC/32, CC/32), tb>>>(W_cm, wcm, CC, 4*CC);
    transpose_h<<<dim3(CC/32, 4*CC/32), tb>>>(W_cp, wcp, 4*CC, CC);

    // 1) LN1 -> fp16
    ln1_kernel<<<MM, 256>>>(x, g1, b1, xn);
    // 2) GEMM1 + time-mix epilogue -> kvr (fp32)
    mma_gemm<1><<<dim3(3*CC/128, MM/256), 512, GSMEM>>>(
        xn, wtm, CC, kvr, nullptr, x, tmk, tmv, tmr);
    // 3) WKV scan -> x1, state tail of out
    wkv_kernel<<<(BB*CC)/64, 64>>>(kvr, x, tdec, tfir, x1, out + (size_t)MM * CC);
    // 4) LN2 + rr gate -> fp16 + rr
    ln2_rr_kernel<<<MM, 256>>>(x1, g2, b2, cmr, xn2, rr);
    // 5) GEMM2 + channel-mix relu^2 epilogue -> hidden fp16
    mma_gemm<2><<<dim3(4*CC/128, MM/256), 512, GSMEM>>>(
        xn2, wcm, CC, nullptr, hid, x1, cmk, nullptr, nullptr);
    // 6) GEMM3 + final epilogue -> out = x1 + rr*vv
    mma_gemm<3><<<dim3(CC/128, MM/256), 512, GSMEM>>>(
        hid, wcp, 4*CC, out, nullptr, x1, rr, nullptr, nullptr);
}

// round 8
// speedup vs baseline: 5.0248x; 1.4156x over previous
#include <cuda_runtime.h>
#include <cuda_fp16.h>
#include <cuda_bf16.h>
#include <cstdint>

#define BB 8
#define TT 2048
#define CC 1024
#define MM (BB*TT)          // 16384 rows

// ---------------- scratch (static device arrays; no allocation) -------------
__device__ float g_kvr[(size_t)MM * 3 * CC];
__device__ float g_x1 [(size_t)MM * CC];
__device__ float g_rr [(size_t)MM * CC];
__device__ __half g_xn  [(size_t)MM * CC];
__device__ __half g_xn2 [(size_t)MM * CC];
__device__ __half g_hid [(size_t)MM * 4 * CC];
__device__ __half g_wtm [(size_t)3 * CC * CC];   // W_tm^T  [3C, C]
__device__ __half g_wcm [(size_t)4 * CC * CC];   // W_cm^T  [4C, C]
__device__ __half g_wcp [(size_t)CC * 4 * CC];   // W_cp^T  [C, 4C]

__device__ __forceinline__ float sigmoidf_(float z) {
    return 1.0f / (1.0f + __expf(-z));
}
__device__ __forceinline__ uint32_t smem_u32(const void* p) {
    uint32_t a;
    asm("{ .reg .u64 t; cvta.to.shared.u64 t, %1; cvt.u32.u64 %0, t; }"
        : "=r"(a) : "l"(p));
    return a;
}
__device__ __forceinline__ void cp16(uint32_t sa, const void* ga) {
    asm volatile("cp.async.cg.shared.global [%0], [%1], 16;"
                 :: "r"(sa), "l"(ga) : "memory");
}
__device__ __forceinline__ void cp_commit() {
    asm volatile("cp.async.commit_group;" ::: "memory");
}
__device__ __forceinline__ void ldx4(uint32_t* r, uint32_t addr) {
    asm volatile("ldmatrix.sync.aligned.m8n8.x4.shared.b16 {%0,%1,%2,%3}, [%4];"
                 : "=r"(r[0]), "=r"(r[1]), "=r"(r[2]), "=r"(r[3]) : "r"(addr));
}
__device__ __forceinline__ void mma16816(float* c, const uint32_t* a,
                                         uint32_t b0, uint32_t b1) {
    asm volatile(
        "mma.sync.aligned.m16n8k16.row.col.f32.f16.f16.f32 "
        "{%0,%1,%2,%3}, {%4,%5,%6,%7}, {%8,%9}, {%0,%1,%2,%3};"
        : "+f"(c[0]), "+f"(c[1]), "+f"(c[2]), "+f"(c[3])
        : "r"(a[0]), "r"(a[1]), "r"(a[2]), "r"(a[3]), "r"(b0), "r"(b1));
}

// ---------------- weight transpose -> fp16 -----------------------------------
__global__ void transpose_h(const float* __restrict__ W,
                            __half* __restrict__ Th, int K, int N) {
    __shared__ float tile[32][33];
    int n0 = blockIdx.x * 32, k0 = blockIdx.y * 32;
    int tx = threadIdx.x, ty = threadIdx.y;  // 32 x 8
    #pragma unroll
    for (int i = 0; i < 32; i += 8)
        tile[ty + i][tx] = W[(size_t)(k0 + ty + i) * N + n0 + tx];
    __syncthreads();
    #pragma unroll
    for (int i = 0; i < 32; i += 8)
        Th[(size_t)(n0 + ty + i) * K + k0 + tx] = __float2half_rn(tile[tx][ty + i]);
}

// ---------------- LayerNorm 1 -> fp16 ----------------------------------------
__global__ void ln1_kernel(const float* __restrict__ x,
                           const float* __restrict__ g,
                           const float* __restrict__ b,
                           __half* __restrict__ oh) {
    int row = blockIdx.x;
    float4 v = ((const float4*)(x + (size_t)row * CC))[threadIdx.x];
    float s = v.x + v.y + v.z + v.w;
    float q = v.x*v.x + v.y*v.y + v.z*v.z + v.w*v.w;
    int lane = threadIdx.x & 31, wid = threadIdx.x >> 5;
    #pragma unroll
    for (int o = 16; o; o >>= 1) {
        s += __shfl_xor_sync(0xffffffffu, s, o);
        q += __shfl_xor_sync(0xffffffffu, q, o);
    }
    __shared__ float s_s[8], s_q[8];
    if (!lane) { s_s[wid] = s; s_q[wid] = q; }
    __syncthreads();
    if (threadIdx.x == 0) {
        float a = 0.f, c2 = 0.f;
        #pragma unroll
        for (int i = 0; i < 8; i++) { a += s_s[i]; c2 += s_q[i]; }
        s_s[0] = a; s_q[0] = c2;
    }
    __syncthreads();
    float mean = s_s[0] * (1.0f / CC);
    float var  = s_q[0] * (1.0f / CC) - mean * mean;
    float rstd = rsqrtf(var + 1e-5f);
    float4 gv = ((const float4*)g)[threadIdx.x];
    float4 bv = ((const float4*)b)[threadIdx.x];
    __half2 h01 = __floats2half2_rn((v.x - mean) * rstd * gv.x + bv.x,
                                    (v.y - mean) * rstd * gv.y + bv.y);
    __half2 h23 = __floats2half2_rn((v.z - mean) * rstd * gv.z + bv.z,
                                    (v.w - mean) * rstd * gv.w + bv.w);
    __half2* ph = (__half2*)(oh + (size_t)row * CC);
    ph[threadIdx.x * 2] = h01;  ph[threadIdx.x * 2 + 1] = h23;
}

// ---------------- LayerNorm 2 + rr gate -> fp16 ------------------------------
__global__ void ln2_rr_kernel(const float* __restrict__ x1,
                              const float* __restrict__ g,
                              const float* __restrict__ b,
                              const float* __restrict__ cmr,
                              __half* __restrict__ oh,
                              float* __restrict__ rr) {
    int row = blockIdx.x;
    float4 v = ((const float4*)(x1 + (size_t)row * CC))[threadIdx.x];
    float s = v.x + v.y + v.z + v.w;
    float q = v.x*v.x + v.y*v.y + v.z*v.z + v.w*v.w;
    int lane = threadIdx.x & 31, wid = threadIdx.x >> 5;
    #pragma unroll
    for (int o = 16; o; o >>= 1) {
        s += __shfl_xor_sync(0xffffffffu, s, o);
        q += __shfl_xor_sync(0xffffffffu, q, o);
    }
    __shared__ float s_s[8], s_q[8];
    if (!lane) { s_s[wid] = s; s_q[wid] = q; }
    __syncthreads();
    if (threadIdx.x == 0) {
        float a = 0.f, c2 = 0.f;
        #pragma unroll
        for (int i = 0; i < 8; i++) { a += s_s[i]; c2 += s_q[i]; }
        s_s[0] = a; s_q[0] = c2;
    }
    __syncthreads();
    float mean = s_s[0] * (1.0f / CC);
    float var  = s_q[0] * (1.0f / CC) - mean * mean;
    float rstd = rsqrtf(var + 1e-5f);
    float4 gv = ((const float4*)g)[threadIdx.x];
    float4 bv = ((const float4*)b)[threadIdx.x];
    float o0 = (v.x - mean) * rstd * gv.x + bv.x;
    float o1 = (v.y - mean) * rstd * gv.y + bv.y;
    float o2 = (v.z - mean) * rstd * gv.z + bv.z;
    float o3 = (v.w - mean) * rstd * gv.w + bv.w;
    __half2* ph = (__half2*)(oh + (size_t)row * CC);
    ph[threadIdx.x * 2]     = __floats2half2_rn(o0, o1);
    ph[threadIdx.x * 2 + 1] = __floats2half2_rn(o2, o3);

    int t = row & (TT - 1);
    int prow = (t == 0) ? (row + TT - 1) : (row - 1);
    float4 xp = ((const float4*)(x1 + (size_t)prow * CC))[threadIdx.x];
    float4 cr = ((const float4*)cmr)[threadIdx.x];
    float4 r4;
    r4.x = sigmoidf_(xp.x + cr.x * (o0 - xp.x));
    r4.y = sigmoidf_(xp.y + cr.y * (o1 - xp.y));
    r4.z = sigmoidf_(xp.z + cr.z * (o2 - xp.z));
    r4.w = sigmoidf_(xp.w + cr.w * (o3 - xp.w));
    ((float4*)(rr + (size_t)row * CC))[threadIdx.x] = r4;
}

// ---------------- WKV scan (fused x1 = x + r*y) ------------------------------
#define PF 8
__global__ void wkv_kernel(const float* __restrict__ kvr,
                           const float* __restrict__ x,
                           const float* __restrict__ wd,
                           const float* __restrict__ uf,
                           float* __restrict__ x1,
                           float* __restrict__ out_state) {
    int gid = blockIdx.x * blockDim.x + threadIdx.x;
    int b = gid >> 10, c = gid & (CC - 1);
    float w = wd[c], u = uf[c];
    float aa = 0.0f, bb = -1e38f;
    size_t kbase = (size_t)b * TT * (3 * CC) + c;
    size_t xbase = (size_t)b * TT * CC + c;

    float pk[PF], pv[PF], pr[PF], px[PF];
    #pragma unroll
    for (int i = 0; i < PF; i++) {
        size_t ko = kbase + (size_t)i * (3 * CC);
        pk[i] = kvr[ko];  pv[i] = kvr[ko + CC];  pr[i] = kvr[ko + 2 * CC];
        px[i] = x[xbase + (size_t)i * CC];
    }
    for (int t0 = 0; t0 < TT; t0 += PF) {
        #pragma unroll
        for (int i = 0; i < PF; i++) {
            int t = t0 + i;
            float kk = pk[i], vv = pv[i], r = pr[i], xv = px[i];
            int tn = t + PF;
            if (tn < TT) {
                size_t ko = kbase + (size_t)tn * (3 * CC);
                pk[i] = kvr[ko];  pv[i] = kvr[ko + CC];  pr[i] = kvr[ko + 2 * CC];
                px[i] = x[xbase + (size_t)tn * CC];
            }
            float ww = u + kk;
            float p  = fmaxf(bb, ww);
            float e1 = __expf(bb - p);
            float e2 = __expf(ww - p);
            float y  = __fdividef(e1 * aa + e2 * vv, e1 + e2 + 1e-8f);
            x1[xbase + (size_t)t * CC] = xv + r * y;
            float w2 = w + bb;
            float p2 = fmaxf(w2, kk);
            float ea = __expf(w2 - p2);
            float eb = __expf(kk - p2);
            aa = ea * aa + eb * vv;
            bb = p2 + __logf(ea + eb + 1e-8f);
        }
    }
    out_state[(size_t)gid * 2 + 0] = aa;
    out_state[(size_t)gid * 2 + 1] = bb;
}

// ---------------- HMMA GEMM: C[128,256] = A[128,K] @ B[256,K]^T --------------
// fp16 inputs, fp32 accumulate. cp.async 3-stage, BK=64.
// 256 threads = 8 warps, warp tile 64x64 (wm=warp>>2 in 0..1, wn=warp&3 in 0..3).
// Register double-buffered ldmatrix fragments hide LDS latency from HMMA.
#define BKG 64
#define STAGES 3
#define STG_BYTES 49152            // A 128x64x2 = 16KB | B 256x64x2 = 32KB
#define GSMEM (STAGES * STG_BYTES)

template <int EPI>
__global__ void __launch_bounds__(256, 1)
mma_gemm(const __half* __restrict__ A, const __half* __restrict__ B,
         int K,
         float* __restrict__ outf, __half* __restrict__ outh,
         const float* __restrict__ e0, const float* __restrict__ e1,
         const float* __restrict__ e2, const float* __restrict__ e3) {
    extern __shared__ char smem[];
    const int tid = threadIdx.x;
    const int m0 = blockIdx.y * 128;
    const int n0 = blockIdx.x * 256;
    uint32_t sb = smem_u32(smem);
    const int warp = tid >> 5, lane = tid & 31;
    const int wm = warp >> 2, wn = warp & 3;   // warp tile: 64(m) x 64(n)

    float acc[4][8][4];
    #pragma unroll
    for (int i = 0; i < 4; i++)
        #pragma unroll
        for (int j = 0; j < 8; j++)
            #pragma unroll
            for (int e = 0; e < 4; e++) acc[i][j][e] = 0.f;

    const __half* Ab = A + (size_t)m0 * K;
    const __half* Bb = B + (size_t)n0 * K;
    const int crow = tid >> 3;            // 0..31
    const int ccol = tid & 7;             // 16B chunk 0..7

    auto copy_stage = [&](int ks, int buf) {
        int k0 = ks * BKG;
        uint32_t base = sb + (uint32_t)buf * STG_BYTES;
        #pragma unroll
        for (int i = 0; i < 4; i++) {     // A: 128 rows
            int row = i * 32 + crow;
            uint32_t sa = base + (uint32_t)row * 128 + (uint32_t)((ccol ^ (row & 7)) << 4);
            cp16(sa, Ab + (size_t)row * K + k0 + ccol * 8);
        }
        #pragma unroll
        for (int i = 0; i < 8; i++) {     // B: 256 rows
            int row = i * 32 + crow;
            uint32_t sa = base + 16384 + (uint32_t)row * 128 + (uint32_t)((ccol ^ (row & 7)) << 4);
            cp16(sa, Bb + (size_t)row * K + k0 + ccol * 8);
        }
        cp_commit();
    };

    copy_stage(0, 0);
    copy_stage(1, 1);

    // Fragment smem addresses: row fixed per fragment; only kk varies.
    // addr(kk) = base_const + (((kk*2 + (lane>>4))<<4) ^ ((row&7)<<4))
    const int lhalf = (lane >> 4) << 4;          // 0 or 16
    uint32_t a_base[4], b_base[4];
    uint32_t a_sw[4], b_sw[4];
    #pragma unroll
    for (int mi = 0; mi < 4; mi++) {
        int row = wm * 64 + mi * 16 + (lane & 15);
        a_base[mi] = (uint32_t)row * 128;
        a_sw[mi]   = (uint32_t)((row & 7) << 4);
    }
    #pragma unroll
    for (int nq = 0; nq < 4; nq++) {
        int row = wn * 64 + nq * 16 + (lane & 15);
        b_base[nq] = 16384u + (uint32_t)row * 128;
        b_sw[nq]   = (uint32_t)((row & 7) << 4);
    }

    uint32_t afr[2][4][4];     // [buf][mi][4 regs]
    uint32_t bfr[2][4][4];     // [buf][nq][4 regs]

    auto load_frags = [&](uint32_t bufb, int kk, int fb) {
        uint32_t ch = (uint32_t)(kk * 32 + lhalf);
        #pragma unroll
        for (int mi = 0; mi < 4; mi++)
            ldx4(afr[fb][mi], bufb + a_base[mi] + (ch ^ a_sw[mi]));
        #pragma unroll
        for (int nq = 0; nq < 4; nq++)
            ldx4(bfr[fb][nq], bufb + b_base[nq] + (ch ^ b_sw[nq]));
    };
    auto do_mmas = [&](int fb) {
        #pragma unroll
        for (int mi = 0; mi < 4; mi++)
            #pragma unroll
            for (int nq = 0; nq < 4; nq++) {
                // nq covers n8 pairs (2*nq, 2*nq+1)
                mma16816(acc[mi][2*nq+0], afr[fb][mi], bfr[fb][nq][0], bfr[fb][nq][2]);
                mma16816(acc[mi][2*nq+1], afr[fb][mi], bfr[fb][nq][1], bfr[fb][nq][3]);
            }
    };

    const int NK = K / BKG;
    for (int ks = 0; ks < NK; ks++) {
        asm volatile("cp.async.wait_group 1;" ::: "memory");
        __syncthreads();
        if (ks + STAGES - 1 < NK) copy_stage(ks + STAGES - 1, (ks + STAGES - 1) % STAGES);
        else cp_commit();   // uniform group count: wait_group 1 => current ready

        uint32_t bufb = sb + (uint32_t)(ks % STAGES) * STG_BYTES;
        load_frags(bufb, 0, 0);
        #pragma unroll
        for (int kk = 0; kk < 4; kk++) {
            if (kk < 3) load_frags(bufb, kk + 1, (kk + 1) & 1);
            do_mmas(kk & 1);
        }
    }

    // ---------------- fused epilogue -----------------------------------------
    const int qr = lane >> 2;        // 0..7
    const int qe = lane & 3;         // 0..3
    #pragma unroll
    for (int mi = 0; mi < 4; mi++) {
        #pragma unroll
        for (int rh = 0; rh < 2; rh++) {
            int m = m0 + wm * 64 + mi * 16 + qr + rh * 8;
            int t = m & (TT - 1);
            if (EPI == 1) {
                int seg = n0 >> 10;
                const float* coefp = (seg == 0) ? e1 : (seg == 1) ? e2 : e3;
                int pm = t ? (m - 1) : m;
                const float* xpr = e0 + (size_t)pm * CC;
                float* orow = outf + (size_t)m * (3 * CC);
                #pragma unroll
                for (int nj = 0; nj < 8; nj++) {
                    int n = n0 + wn * 64 + nj * 8 + 2 * qe;
                    int c = n & (CC - 1);
                    float v0 = acc[mi][nj][rh * 2 + 0];
                    float v1 = acc[mi][nj][rh * 2 + 1];
                    float x0 = xpr[c], x1v = xpr[c + 1];
                    float a0 = x0  + coefp[c]     * (v0 - x0);
                    float a1 = x1v + coefp[c + 1] * (v1 - x1v);
                    if (seg == 2) { a0 = sigmoidf_(a0); a1 = sigmoidf_(a1); }
                    float2 o = {a0, a1};
                    *(float2*)(orow + n) = o;
                }
            } else if (EPI == 2) {
                int pm = t ? (m - 1) : (m + TT - 1);
                const float* xpr = e0 + (size_t)pm * CC;
                size_t rowo = (size_t)m * (4 * CC);
                #pragma unroll
                for (int nj = 0; nj < 8; nj++) {
                    int n = n0 + wn * 64 + nj * 8 + 2 * qe;
                    int c = n & (CC - 1);
                    float v0 = acc[mi][nj][rh * 2 + 0];
                    float v1 = acc[mi][nj][rh * 2 + 1];
                    float x0 = xpr[c], x1v = xpr[c + 1];
                    float a0 = fmaxf(x0  + e1[c]     * (v0 - x0), 0.f);
                    float a1 = fmaxf(x1v + e1[c + 1] * (v1 - x1v), 0.f);
                    *(__half2*)(outh + rowo + n) = __floats2half2_rn(a0 * a0, a1 * a1);
                }
            } else {
                size_t rowo = (size_t)m * CC;
                #pragma unroll
                for (int nj = 0; nj < 8; nj++) {
                    int n = n0 + wn * 64 + nj * 8 + 2 * qe;
                    float2 xv = *(const float2*)(e0 + rowo + n);
                    float2 rv = *(const float2*)(e1 + rowo + n);
                    float2 o;
                    o.x = xv.x + rv.x * acc[mi][nj][rh * 2 + 0];
                    o.y = xv.y + rv.y * acc[mi][nj][rh * 2 + 1];
                    *(float2*)(outf + rowo + n) = o;
                }
            }
        }
    }
}

// ---------------- launch ------------------------------------------------------
extern "C" void kernel_launch(void* const* d_in, const int* in_sizes, int n_in,
                              void* d_out, int out_size) {
    const float* x    = (const float*)d_in[0];
    const float* tdec = (const float*)d_in[1];
    const float* tfir = (const float*)d_in[2];
    const float* W_tm = (const float*)d_in[3];
    const float* g1   = (const float*)d_in[4];
    const float* b1   = (const float*)d_in[5];
    const float* tmk  = (const float*)d_in[6];
    const float* tmv  = (const float*)d_in[7];
    const float* tmr  = (const float*)d_in[8];
    const float* W_cm = (const float*)d_in[9];
    const float* W_cp = (const float*)d_in[10];
    const float* g2   = (const float*)d_in[11];
    const float* b2   = (const float*)d_in[12];
    const float* cmk  = (const float*)d_in[13];
    const float* cmr  = (const float*)d_in[14];
    float* out = (float*)d_out;

    float *kvr, *x1, *rr;
    __half *xn, *xn2, *hid, *wtm, *wcm, *wcp;
    cudaGetSymbolAddress((void**)&kvr, g_kvr);
    cudaGetSymbolAddress((void**)&x1,  g_x1);
    cudaGetSymbolAddress((void**)&rr,  g_rr);
    cudaGetSymbolAddress((void**)&xn,  g_xn);
    cudaGetSymbolAddress((void**)&xn2, g_xn2);
    cudaGetSymbolAddress((void**)&hid, g_hid);
    cudaGetSymbolAddress((void**)&wtm, g_wtm);
    cudaGetSymbolAddress((void**)&wcm, g_wcm);
    cudaGetSymbolAddress((void**)&wcp, g_wcp);

    cudaFuncSetAttribute(mma_gemm<1>, cudaFuncAttributeMaxDynamicSharedMemorySize, GSMEM);
    cudaFuncSetAttribute(mma_gemm<2>, cudaFuncAttributeMaxDynamicSharedMemorySize, GSMEM);
    cudaFuncSetAttribute(mma_gemm<3>, cudaFuncAttributeMaxDynamicSharedMemorySize, GSMEM);

    dim3 tb(32, 8);
    transpose_h<<<dim3(3*CC/32, CC/32), tb>>>(W_tm, wtm, CC, 3*CC);
    transpose_h<<<dim3(4*CC/32, CC/32), tb>>>(W_cm, wcm, CC, 4*CC);
    transpose_h<<<dim3(CC/32, 4*CC/32), tb>>>(W_cp, wcp, 4*CC, CC);

    // 1) LN1 -> fp16
    ln1_kernel<<<MM, 256>>>(x, g1, b1, xn);
    // 2) GEMM1 + time-mix epilogue -> kvr (fp32)
    mma_gemm<1><<<dim3(3*CC/256, MM/128), 256, GSMEM>>>(
        xn, wtm, CC, kvr, nullptr, x, tmk, tmv, tmr);
    // 3) WKV scan -> x1, state tail of out
    wkv_kernel<<<(BB*CC)/64, 64>>>(kvr, x, tdec, tfir, x1, out + (size_t)MM * CC);
    // 4) LN2 + rr gate -> fp16 + rr
    ln2_rr_kernel<<<MM, 256>>>(x1, g2, b2, cmr, xn2, rr);
    // 5) GEMM2 + channel-mix relu^2 epilogue -> hidden fp16
    mma_gemm<2><<<dim3(4*CC/256, MM/128), 256, GSMEM>>>(
        xn2, wcm, CC, nullptr, hid, x1, cmk, nullptr, nullptr);
    // 6) GEMM3 + final epilogue -> out = x1 + rr*vv
    mma_gemm<3><<<dim3(CC/256, MM/128), 256, GSMEM>>>(
        hid, wcp, 4*CC, out, nullptr, x1, rr, nullptr, nullptr);
}

// round 9
// speedup vs baseline: 5.2880x; 1.0524x over previous
#include <cuda_runtime.h>
#include <cuda_fp16.h>
#include <cuda_bf16.h>
#include <cstdint>

#define BB 8
#define TT 2048
#define CC 1024
#define MM (BB*TT)          // 16384 rows

// ---------------- scratch (static device arrays; no allocation) -------------
__device__ float g_kvr[(size_t)MM * 3 * CC];
__device__ float g_x1 [(size_t)MM * CC];
__device__ float g_rr [(size_t)MM * CC];
__device__ __half g_xn  [(size_t)MM * CC];
__device__ __half g_xn2 [(size_t)MM * CC];
__device__ __half g_hid [(size_t)MM * 4 * CC];
__device__ __half g_wtm [(size_t)3 * CC * CC];   // W_tm^T  [3C, C]
__device__ __half g_wcm [(size_t)4 * CC * CC];   // W_cm^T  [4C, C]
__device__ __half g_wcp [(size_t)CC * 4 * CC];   // W_cp^T  [C, 4C]

__device__ __forceinline__ float sigmoidf_(float z) {
    return 1.0f / (1.0f + __expf(-z));
}
__device__ __forceinline__ uint32_t smem_u32(const void* p) {
    uint32_t a;
    asm("{ .reg .u64 t; cvta.to.shared.u64 t, %1; cvt.u32.u64 %0, t; }"
        : "=r"(a) : "l"(p));
    return a;
}
__device__ __forceinline__ void cp16(uint32_t sa, const void* ga) {
    asm volatile("cp.async.cg.shared.global [%0], [%1], 16;"
                 :: "r"(sa), "l"(ga) : "memory");
}
__device__ __forceinline__ void cp_commit() {
    asm volatile("cp.async.commit_group;" ::: "memory");
}
__device__ __forceinline__ void ldx4(uint32_t* r, uint32_t addr) {
    asm volatile("ldmatrix.sync.aligned.m8n8.x4.shared.b16 {%0,%1,%2,%3}, [%4];"
                 : "=r"(r[0]), "=r"(r[1]), "=r"(r[2]), "=r"(r[3]) : "r"(addr));
}
__device__ __forceinline__ void mma16816(float* c, const uint32_t* a,
                                         uint32_t b0, uint32_t b1) {
    asm volatile(
        "mma.sync.aligned.m16n8k16.row.col.f32.f16.f16.f32 "
        "{%0,%1,%2,%3}, {%4,%5,%6,%7}, {%8,%9}, {%0,%1,%2,%3};"
        : "+f"(c[0]), "+f"(c[1]), "+f"(c[2]), "+f"(c[3])
        : "r"(a[0]), "r"(a[1]), "r"(a[2]), "r"(a[3]), "r"(b0), "r"(b1));
}

// ---------------- weight transpose -> fp16 -----------------------------------
__global__ void transpose_h(const float* __restrict__ W,
                            __half* __restrict__ Th, int K, int N) {
    __shared__ float tile[32][33];
    int n0 = blockIdx.x * 32, k0 = blockIdx.y * 32;
    int tx = threadIdx.x, ty = threadIdx.y;  // 32 x 8
    #pragma unroll
    for (int i = 0; i < 32; i += 8)
        tile[ty + i][tx] = W[(size_t)(k0 + ty + i) * N + n0 + tx];
    __syncthreads();
    #pragma unroll
    for (int i = 0; i < 32; i += 8)
        Th[(size_t)(n0 + ty + i) * K + k0 + tx] = __float2half_rn(tile[tx][ty + i]);
}

// ---------------- LayerNorm 1 -> fp16 ----------------------------------------
__global__ void ln1_kernel(const float* __restrict__ x,
                           const float* __restrict__ g,
                           const float* __restrict__ b,
                           __half* __restrict__ oh) {
    int row = blockIdx.x;
    float4 v = ((const float4*)(x + (size_t)row * CC))[threadIdx.x];
    float s = v.x + v.y + v.z + v.w;
    float q = v.x*v.x + v.y*v.y + v.z*v.z + v.w*v.w;
    int lane = threadIdx.x & 31, wid = threadIdx.x >> 5;
    #pragma unroll
    for (int o = 16; o; o >>= 1) {
        s += __shfl_xor_sync(0xffffffffu, s, o);
        q += __shfl_xor_sync(0xffffffffu, q, o);
    }
    __shared__ float s_s[8], s_q[8];
    if (!lane) { s_s[wid] = s; s_q[wid] = q; }
    __syncthreads();
    if (threadIdx.x == 0) {
        float a = 0.f, c2 = 0.f;
        #pragma unroll
        for (int i = 0; i < 8; i++) { a += s_s[i]; c2 += s_q[i]; }
        s_s[0] = a; s_q[0] = c2;
    }
    __syncthreads();
    float mean = s_s[0] * (1.0f / CC);
    float var  = s_q[0] * (1.0f / CC) - mean * mean;
    float rstd = rsqrtf(var + 1e-5f);
    float4 gv = ((const float4*)g)[threadIdx.x];
    float4 bv = ((const float4*)b)[threadIdx.x];
    __half2 h01 = __floats2half2_rn((v.x - mean) * rstd * gv.x + bv.x,
                                    (v.y - mean) * rstd * gv.y + bv.y);
    __half2 h23 = __floats2half2_rn((v.z - mean) * rstd * gv.z + bv.z,
                                    (v.w - mean) * rstd * gv.w + bv.w);
    __half2* ph = (__half2*)(oh + (size_t)row * CC);
    ph[threadIdx.x * 2] = h01;  ph[threadIdx.x * 2 + 1] = h23;
}

// ---------------- LayerNorm 2 + rr gate -> fp16 ------------------------------
__global__ void ln2_rr_kernel(const float* __restrict__ x1,
                              const float* __restrict__ g,
                              const float* __restrict__ b,
                              const float* __restrict__ cmr,
                              __half* __restrict__ oh,
                              float* __restrict__ rr) {
    int row = blockIdx.x;
    float4 v = ((const float4*)(x1 + (size_t)row * CC))[threadIdx.x];
    float s = v.x + v.y + v.z + v.w;
    float q = v.x*v.x + v.y*v.y + v.z*v.z + v.w*v.w;
    int lane = threadIdx.x & 31, wid = threadIdx.x >> 5;
    #pragma unroll
    for (int o = 16; o; o >>= 1) {
        s += __shfl_xor_sync(0xffffffffu, s, o);
        q += __shfl_xor_sync(0xffffffffu, q, o);
    }
    __shared__ float s_s[8], s_q[8];
    if (!lane) { s_s[wid] = s; s_q[wid] = q; }
    __syncthreads();
    if (threadIdx.x == 0) {
        float a = 0.f, c2 = 0.f;
        #pragma unroll
        for (int i = 0; i < 8; i++) { a += s_s[i]; c2 += s_q[i]; }
        s_s[0] = a; s_q[0] = c2;
    }
    __syncthreads();
    float mean = s_s[0] * (1.0f / CC);
    float var  = s_q[0] * (1.0f / CC) - mean * mean;
    float rstd = rsqrtf(var + 1e-5f);
    float4 gv = ((const float4*)g)[threadIdx.x];
    float4 bv = ((const float4*)b)[threadIdx.x];
    float o0 = (v.x - mean) * rstd * gv.x + bv.x;
    float o1 = (v.y - mean) * rstd * gv.y + bv.y;
    float o2 = (v.z - mean) * rstd * gv.z + bv.z;
    float o3 = (v.w - mean) * rstd * gv.w + bv.w;
    __half2* ph = (__half2*)(oh + (size_t)row * CC);
    ph[threadIdx.x * 2]     = __floats2half2_rn(o0, o1);
    ph[threadIdx.x * 2 + 1] = __floats2half2_rn(o2, o3);

    int t = row & (TT - 1);
    int prow = (t == 0) ? (row + TT - 1) : (row - 1);
    float4 xp = ((const float4*)(x1 + (size_t)prow * CC))[threadIdx.x];
    float4 cr = ((const float4*)cmr)[threadIdx.x];
    float4 r4;
    r4.x = sigmoidf_(xp.x + cr.x * (o0 - xp.x));
    r4.y = sigmoidf_(xp.y + cr.y * (o1 - xp.y));
    r4.z = sigmoidf_(xp.z + cr.z * (o2 - xp.z));
    r4.w = sigmoidf_(xp.w + cr.w * (o3 - xp.w));
    ((float4*)(rr + (size_t)row * CC))[threadIdx.x] = r4;
}

// ---------------- WKV scan (fused x1 = x + r*y) ------------------------------
#define PF 8
__global__ void wkv_kernel(const float* __restrict__ kvr,
                           const float* __restrict__ x,
                           const float* __restrict__ wd,
                           const float* __restrict__ uf,
                           float* __restrict__ x1,
                           float* __restrict__ out_state) {
    int gid = blockIdx.x * blockDim.x + threadIdx.x;
    int b = gid >> 10, c = gid & (CC - 1);
    float w = wd[c], u = uf[c];
    float aa = 0.0f, bb = -1e38f;
    size_t kbase = (size_t)b * TT * (3 * CC) + c;
    size_t xbase = (size_t)b * TT * CC + c;

    float pk[PF], pv[PF], pr[PF], px[PF];
    #pragma unroll
    for (int i = 0; i < PF; i++) {
        size_t ko = kbase + (size_t)i * (3 * CC);
        pk[i] = kvr[ko];  pv[i] = kvr[ko + CC];  pr[i] = kvr[ko + 2 * CC];
        px[i] = x[xbase + (size_t)i * CC];
    }
    for (int t0 = 0; t0 < TT; t0 += PF) {
        #pragma unroll
        for (int i = 0; i < PF; i++) {
            int t = t0 + i;
            float kk = pk[i], vv = pv[i], r = pr[i], xv = px[i];
            int tn = t + PF;
            if (tn < TT) {
                size_t ko = kbase + (size_t)tn * (3 * CC);
                pk[i] = kvr[ko];  pv[i] = kvr[ko + CC];  pr[i] = kvr[ko + 2 * CC];
                px[i] = x[xbase + (size_t)tn * CC];
            }
            float ww = u + kk;
            float p  = fmaxf(bb, ww);
            float e1 = __expf(bb - p);
            float e2 = __expf(ww - p);
            float y  = __fdividef(e1 * aa + e2 * vv, e1 + e2 + 1e-8f);
            x1[xbase + (size_t)t * CC] = xv + r * y;
            float w2 = w + bb;
            float p2 = fmaxf(w2, kk);
            float ea = __expf(w2 - p2);
            float eb = __expf(kk - p2);
            aa = ea * aa + eb * vv;
            bb = p2 + __logf(ea + eb + 1e-8f);
        }
    }
    out_state[(size_t)gid * 2 + 0] = aa;
    out_state[(size_t)gid * 2 + 1] = bb;
}

// ---------------- HMMA GEMM: C[128,256] = A[128,K] @ B[256,K]^T --------------
// fp16 inputs, fp32 accumulate. cp.async 3-stage, BK=64.
// 256 threads = 8 warps, warp tile 64x64. Register double-buffered fragments,
// software-pipelined ACROSS the BK loop: next stage's k0 frags load under the
// last k-step's MMAs, so the loop-head LDSM latency bubble disappears.
#define BKG 64
#define STAGES 3
#define STG_BYTES 49152            // A 128x64x2 = 16KB | B 256x64x2 = 32KB
#define GSMEM (STAGES * STG_BYTES)

template <int EPI>
__global__ void __launch_bounds__(256, 1)
mma_gemm(const __half* __restrict__ A, const __half* __restrict__ B,
         int K,
         float* __restrict__ outf, __half* __restrict__ outh,
         const float* __restrict__ e0, const float* __restrict__ e1,
         const float* __restrict__ e2, const float* __restrict__ e3) {
    extern __shared__ char smem[];
    const int tid = threadIdx.x;
    const int m0 = blockIdx.y * 128;
    const int n0 = blockIdx.x * 256;
    uint32_t sb = smem_u32(smem);
    const int warp = tid >> 5, lane = tid & 31;
    const int wm = warp >> 2, wn = warp & 3;   // warp tile: 64(m) x 64(n)

    float acc[4][8][4];
    #pragma unroll
    for (int i = 0; i < 4; i++)
        #pragma unroll
        for (int j = 0; j < 8; j++)
            #pragma unroll
            for (int e = 0; e < 4; e++) acc[i][j][e] = 0.f;

    const __half* Ab = A + (size_t)m0 * K;
    const __half* Bb = B + (size_t)n0 * K;
    const int crow = tid >> 3;            // 0..31
    const int ccol = tid & 7;             // 16B chunk 0..7

    auto copy_stage = [&](int ks, int buf) {
        int k0 = ks * BKG;
        uint32_t base = sb + (uint32_t)buf * STG_BYTES;
        #pragma unroll
        for (int i = 0; i < 4; i++) {     // A: 128 rows
            int row = i * 32 + crow;
            uint32_t sa = base + (uint32_t)row * 128 + (uint32_t)((ccol ^ (row & 7)) << 4);
            cp16(sa, Ab + (size_t)row * K + k0 + ccol * 8);
        }
        #pragma unroll
        for (int i = 0; i < 8; i++) {     // B: 256 rows
            int row = i * 32 + crow;
            uint32_t sa = base + 16384 + (uint32_t)row * 128 + (uint32_t)((ccol ^ (row & 7)) << 4);
            cp16(sa, Bb + (size_t)row * K + k0 + ccol * 8);
        }
        cp_commit();
    };

    copy_stage(0, 0);
    copy_stage(1, 1);

    // Fragment smem addressing: row fixed per fragment; only k-chunk varies.
    const int lhalf = (lane >> 4) << 4;          // 0 or 16
    uint32_t a_base[4], b_base[4];
    uint32_t a_sw[4], b_sw[4];
    #pragma unroll
    for (int mi = 0; mi < 4; mi++) {
        int row = wm * 64 + mi * 16 + (lane & 15);
        a_base[mi] = (uint32_t)row * 128;
        a_sw[mi]   = (uint32_t)((row & 7) << 4);
    }
    #pragma unroll
    for (int nq = 0; nq < 4; nq++) {
        int row = wn * 64 + nq * 16 + (lane & 15);
        b_base[nq] = 16384u + (uint32_t)row * 128;
        b_sw[nq]   = (uint32_t)((row & 7) << 4);
    }

    uint32_t afr[2][4][4];     // [buf][mi][4 regs]
    uint32_t bfr[2][4][4];     // [buf][nq][4 regs]

    auto load_frags = [&](uint32_t bufb, int kk, int fb) {
        uint32_t ch = (uint32_t)(kk * 32 + lhalf);
        #pragma unroll
        for (int mi = 0; mi < 4; mi++)
            ldx4(afr[fb][mi], bufb + a_base[mi] + (ch ^ a_sw[mi]));
        #pragma unroll
        for (int nq = 0; nq < 4; nq++)
            ldx4(bfr[fb][nq], bufb + b_base[nq] + (ch ^ b_sw[nq]));
    };
    auto do_mmas = [&](int fb) {
        #pragma unroll
        for (int mi = 0; mi < 4; mi++)
            #pragma unroll
            for (int nq = 0; nq < 4; nq++) {
                mma16816(acc[mi][2*nq+0], afr[fb][mi], bfr[fb][nq][0], bfr[fb][nq][2]);
                mma16816(acc[mi][2*nq+1], afr[fb][mi], bfr[fb][nq][1], bfr[fb][nq][3]);
            }
    };

    const int NK = K / BKG;
    // Prologue: stage 0 ready, load its k-step 0 fragments.
    asm volatile("cp.async.wait_group 1;" ::: "memory");
    __syncthreads();
    load_frags(sb, 0, 0);

    for (int ks = 0; ks < NK; ks++) {
        uint32_t bufb = sb + (uint32_t)(ks % STAGES) * STG_BYTES;
        #pragma unroll
        for (int kk = 0; kk < 4; kk++) {
            if (kk < 3) {
                load_frags(bufb, kk + 1, (kk + 1) & 1);
            } else if (ks + 1 < NK) {
                // Boundary: protect the stage that copy(ks+2) will overwrite,
                // issue the copy, wait for stage ks+1, prefetch its k0 frags.
                __syncthreads();
                if (ks + 2 < NK) copy_stage(ks + 2, (ks + 2) % STAGES);
                else cp_commit();
                asm volatile("cp.async.wait_group 1;" ::: "memory");
                __syncthreads();
                load_frags(sb + (uint32_t)((ks + 1) % STAGES) * STG_BYTES, 0, 0);
            }
            do_mmas(kk & 1);
        }
    }

    // ---------------- fused epilogue -----------------------------------------
    const int qr = lane >> 2;        // 0..7
    const int qe = lane & 3;         // 0..3
    #pragma unroll
    for (int mi = 0; mi < 4; mi++) {
        #pragma unroll
        for (int rh = 0; rh < 2; rh++) {
            int m = m0 + wm * 64 + mi * 16 + qr + rh * 8;
            int t = m & (TT - 1);
            if (EPI == 1) {
                int seg = n0 >> 10;
                const float* coefp = (seg == 0) ? e1 : (seg == 1) ? e2 : e3;
                int pm = t ? (m - 1) : m;
                const float* xpr = e0 + (size_t)pm * CC;
                float* orow = outf + (size_t)m * (3 * CC);
                #pragma unroll
                for (int nj = 0; nj < 8; nj++) {
                    int n = n0 + wn * 64 + nj * 8 + 2 * qe;
                    int c = n & (CC - 1);
                    float v0 = acc[mi][nj][rh * 2 + 0];
                    float v1 = acc[mi][nj][rh * 2 + 1];
                    float x0 = xpr[c], x1v = xpr[c + 1];
                    float a0 = x0  + coefp[c]     * (v0 - x0);
                    float a1 = x1v + coefp[c + 1] * (v1 - x1v);
                    if (seg == 2) { a0 = sigmoidf_(a0); a1 = sigmoidf_(a1); }
                    float2 o = {a0, a1};
                    *(float2*)(orow + n) = o;
                }
            } else if (EPI == 2) {
                int pm = t ? (m - 1) : (m + TT - 1);
                const float* xpr = e0 + (size_t)pm * CC;
                size_t rowo = (size_t)m * (4 * CC);
                #pragma unroll
                for (int nj = 0; nj < 8; nj++) {
                    int n = n0 + wn * 64 + nj * 8 + 2 * qe;
                    int c = n & (CC - 1);
                    float v0 = acc[mi][nj][rh * 2 + 0];
                    float v1 = acc[mi][nj][rh * 2 + 1];
                    float x0 = xpr[c], x1v = xpr[c + 1];
                    float a0 = fmaxf(x0  + e1[c]     * (v0 - x0), 0.f);
                    float a1 = fmaxf(x1v + e1[c + 1] * (v1 - x1v), 0.f);
                    *(__half2*)(outh + rowo + n) = __floats2half2_rn(a0 * a0, a1 * a1);
                }
            } else {
                size_t rowo = (size_t)m * CC;
                #pragma unroll
                for (int nj = 0; nj < 8; nj++) {
                    int n = n0 + wn * 64 + nj * 8 + 2 * qe;
                    float2 xv = *(const float2*)(e0 + rowo + n);
                    float2 rv = *(const float2*)(e1 + rowo + n);
                    float2 o;
                    o.x = xv.x + rv.x * acc[mi][nj][rh * 2 + 0];
                    o.y = xv.y + rv.y * acc[mi][nj][rh * 2 + 1];
                    *(float2*)(outf + rowo + n) = o;
                }
            }
        }
    }
}

// ---------------- launch ------------------------------------------------------
extern "C" void kernel_launch(void* const* d_in, const int* in_sizes, int n_in,
                              void* d_out, int out_size) {
    const float* x    = (const float*)d_in[0];
    const float* tdec = (const float*)d_in[1];
    const float* tfir = (const float*)d_in[2];
    const float* W_tm = (const float*)d_in[3];
    const float* g1   = (const float*)d_in[4];
    const float* b1   = (const float*)d_in[5];
    const float* tmk  = (const float*)d_in[6];
    const float* tmv  = (const float*)d_in[7];
    const float* tmr  = (const float*)d_in[8];
    const float* W_cm = (const float*)d_in[9];
    const float* W_cp = (const float*)d_in[10];
    const float* g2   = (const float*)d_in[11];
    const float* b2   = (const float*)d_in[12];
    const float* cmk  = (const float*)d_in[13];
    const float* cmr  = (const float*)d_in[14];
    float* out = (float*)d_out;

    float *kvr, *x1, *rr;
    __half *xn, *xn2, *hid, *wtm, *wcm, *wcp;
    cudaGetSymbolAddress((void**)&kvr, g_kvr);
    cudaGetSymbolAddress((void**)&x1,  g_x1);
    cudaGetSymbolAddress((void**)&rr,  g_rr);
    cudaGetSymbolAddress((void**)&xn,  g_xn);
    cudaGetSymbolAddress((void**)&xn2, g_xn2);
    cudaGetSymbolAddress((void**)&hid, g_hid);
    cudaGetSymbolAddress((void**)&wtm, g_wtm);
    cudaGetSymbolAddress((void**)&wcm, g_wcm);
    cudaGetSymbolAddress((void**)&wcp, g_wcp);

    cudaFuncSetAttribute(mma_gemm<1>, cudaFuncAttributeMaxDynamicSharedMemorySize, GSMEM);
    cudaFuncSetAttribute(mma_gemm<2>, cudaFuncAttributeMaxDynamicSharedMemorySize, GSMEM);
    cudaFuncSetAttribute(mma_gemm<3>, cudaFuncAttributeMaxDynamicSharedMemorySize, GSMEM);

    dim3 tb(32, 8);
    transpose_h<<<dim3(3*CC/32, CC/32), tb>>>(W_tm, wtm, CC, 3*CC);
    transpose_h<<<dim3(4*CC/32, CC/32), tb>>>(W_cm, wcm, CC, 4*CC);
    transpose_h<<<dim3(CC/32, 4*CC/32), tb>>>(W_cp, wcp, 4*CC, CC);

    // 1) LN1 -> fp16
    ln1_kernel<<<MM, 256>>>(x, g1, b1, xn);
    // 2) GEMM1 + time-mix epilogue -> kvr (fp32)
    mma_gemm<1><<<dim3(3*CC/256, MM/128), 256, GSMEM>>>(
        xn, wtm, CC, kvr, nullptr, x, tmk, tmv, tmr);
    // 3) WKV scan -> x1, state tail of out
    wkv_kernel<<<(BB*CC)/64, 64>>>(kvr, x, tdec, tfir, x1, out + (size_t)MM * CC);
    // 4) LN2 + rr gate -> fp16 + rr
    ln2_rr_kernel<<<MM, 256>>>(x1, g2, b2, cmr, xn2, rr);
    // 5) GEMM2 + channel-mix relu^2 epilogue -> hidden fp16
    mma_gemm<2><<<dim3(4*CC/256, MM/128), 256, GSMEM>>>(
        xn2, wcm, CC, nullptr, hid, x1, cmk, nullptr, nullptr);
    // 6) GEMM3 + final epilogue -> out = x1 + rr*vv
    mma_gemm<3><<<dim3(CC/256, MM/128), 256, GSMEM>>>(
        hid, wcp, 4*CC, out, nullptr, x1, rr, nullptr, nullptr);
}